// round 11
// baseline (speedup 1.0000x reference)
#include <cuda_runtime.h>
#include <cuda_bf16.h>
#include <cstdint>
#include <math.h>

#define H      2048
#define E      64
#define KTOP   8
#define NTOK   16384
#define SEQ    4096
#define BATCH  4
#define MT     64
#define NBLK   (NTOK / MT)     // 256 CTAs
#define NCH    32              // K chunks of 64
#define GAPTH  8e-6f
#define LSTR   66
#define NTHR   384             // 8 consumer warps + 4 producer warps

// dynamic smem: two 32KB buffers (xhi,xlo,whi,wlo 8KB each)
#define OFF_BUF  1024
#define OA1      0
#define OA2      8192
#define OB1      16384
#define OB2      24576
#define BUF_SZ   32768
#define SMEM_BYTES (OFF_BUF + 2 * BUF_SZ)   // 66560
#define OFF_WST  (OFF_BUF + 20480)          // fixup W stage: float[64][132]

typedef unsigned long long ull;

__device__ float    g_ssum[NBLK][E];
__device__ float    g_cnt [NBLK][E];
__device__ int      g_done;
__device__ __align__(16) uint32_t g_wimg[NCH][2][2048];   // swizzled bf16 hi/lo W images

// ---------------- helpers ----------------
__device__ __forceinline__ uint32_t smem_u32(const void* p) {
    uint32_t a;
    asm("{ .reg .u64 t; cvta.to.shared.u64 t, %1; cvt.u32.u64 %0, t; }" : "=r"(a) : "l"(p));
    return a;
}
__device__ __forceinline__ uint32_t swz(uint32_t b) { return b ^ ((b >> 3) & 0x70); }

#define BAR_SYNC(id)   asm volatile("bar.sync %0, %1;"   :: "r"(id), "r"(NTHR) : "memory")
#define BAR_ARRIVE(id) asm volatile("bar.arrive %0, %1;" :: "r"(id), "r"(NTHR) : "memory")

__device__ __forceinline__ void split2(float f0, float f1, uint32_t& hi, uint32_t& lo) {
    uint32_t h;
    asm("cvt.rn.bf16x2.f32 %0, %1, %2;" : "=r"(h) : "f"(f1), "f"(f0));
    float g0 = __uint_as_float(h << 16);
    float g1 = __uint_as_float(h & 0xFFFF0000u);
    asm("cvt.rn.bf16x2.f32 %0, %1, %2;" : "=r"(lo) : "f"(f1 - g1), "f"(f0 - g0));
    hi = h;
}
__device__ __forceinline__ void ldsm4(uint32_t* r, uint32_t addr) {
    asm volatile("ldmatrix.sync.aligned.m8n8.x4.shared.b16 {%0,%1,%2,%3}, [%4];"
        : "=r"(r[0]), "=r"(r[1]), "=r"(r[2]), "=r"(r[3]) : "r"(addr));
}
__device__ __forceinline__ void mma16816(float* d, const uint32_t* a, const uint32_t* b) {
    asm("mma.sync.aligned.m16n8k16.row.col.f32.bf16.bf16.f32 "
        "{%0,%1,%2,%3}, {%4,%5,%6,%7}, {%8,%9}, {%0,%1,%2,%3};"
        : "+f"(d[0]), "+f"(d[1]), "+f"(d[2]), "+f"(d[3])
        : "r"(a[0]), "r"(a[1]), "r"(a[2]), "r"(a[3]), "r"(b[0]), "r"(b[1]));
}
// ------------------------------------------

// Pre-split W into chunk-local swizzled bf16 hi/lo images.
__global__ __launch_bounds__(256, 1)
void wsplit_kernel(const float* __restrict__ w)
{
    int base = (blockIdx.x * 256 + threadIdx.x) * 4;
#pragma unroll
    for (int j = 0; j < 4; j++) {
        int pid = base + j;               // 0 .. 65535
        int r   = pid >> 10;
        int kp  = pid & 1023;
        int c   = kp >> 5;
        int kk2 = kp & 31;
        float f0 = w[(size_t)r * H + kp * 2];
        float f1 = w[(size_t)r * H + kp * 2 + 1];
        uint32_t hi, lo;
        split2(f0, f1, hi, lo);
        uint32_t off = swz((uint32_t)(r * 128 + kk2 * 4)) >> 2;
        g_wimg[c][0][off] = hi;
        g_wimg[c][1][off] = lo;
    }
}

__global__ __launch_bounds__(NTHR, 2)
void gate_kernel(const float* __restrict__ x,
                 const float* __restrict__ w,
                 float* __restrict__ out)
{
    extern __shared__ __align__(1024) char smem[];
    __shared__ __align__(16) float xst[128];
    __shared__ __align__(16) float part[256];
    __shared__ int cnt[E];
    __shared__ int nflag, flist[MT], islast;

    const uint32_t sb = smem_u32(smem);
    const int tid = threadIdx.x;
    const int wid = tid >> 5;
    const int lid = tid & 31;
    const int m0  = blockIdx.x * MT;

    if (tid == 0) nflag = 0;
    if (tid < E) cnt[tid] = 0;

    float acc[4][4];
#pragma unroll
    for (int t = 0; t < 4; t++)
#pragma unroll
        for (int r = 0; r < 4; r++) acc[t][r] = 0.f;

    // consumer mapping (warps 0-7, same as R10)
    const int mbase = (wid & 3) * 16;
    const int nbase = (wid >> 2) * 32;
    const int arow = lid & 15;
    const int akh  = lid >> 4;
    const int brow = ((lid >> 4) * 8) + (lid & 7);
    const int bkh  = (lid >> 3) & 1;
    const uint32_t relA  = swz((uint32_t)((mbase + arow) * 128 + akh * 16));
    const uint32_t relB0 = swz((uint32_t)((nbase + brow) * 128 + bkh * 16));
    const uint32_t relB1 = swz((uint32_t)((nbase + 16 + brow) * 128 + bkh * 16));

    if (wid >= 8) {
        // ================= PRODUCER warps (8-11; one per SMSP) =================
        const int pt = tid - 256;          // 0..127
        const int pr = pt >> 1;            // token row 0..63
        const int ph = pt & 1;             // 32-col half
        const float* xrow = x + (size_t)(m0 + pr) * H + ph * 32;
        uint32_t xso[4];
#pragma unroll
        for (int q = 0; q < 4; q++)
            xso[q] = swz((uint32_t)(pr * 128 + ph * 64 + q * 16));
        const uint32_t wofs = (uint32_t)pt * 64;

        for (int c = 0; c < NCH; c++) {
            if (c >= 2) BAR_SYNC(3 + (c & 1));       // wait buffer empty
            char* buf = smem + OFF_BUF + (c & 1) * BUF_SZ;

            float4 xv[8];
#pragma unroll
            for (int i = 0; i < 8; i++)
                xv[i] = *(const float4*)(xrow + c * 64 + i * 4);
            uint4 wv0[4], wv1[4];
#pragma unroll
            for (int i = 0; i < 4; i++) {
                wv0[i] = ((const uint4*)&g_wimg[c][0][0])[pt * 4 + i];
                wv1[i] = ((const uint4*)&g_wimg[c][1][0])[pt * 4 + i];
            }
#pragma unroll
            for (int q = 0; q < 4; q++) {
                uint32_t h0, l0, h1, l1;
                split2(xv[2 * q].x, xv[2 * q].y, h0, l0);
                split2(xv[2 * q].z, xv[2 * q].w, h1, l1);
                uint32_t h2, l2, h3, l3;
                split2(xv[2 * q + 1].x, xv[2 * q + 1].y, h2, l2);
                split2(xv[2 * q + 1].z, xv[2 * q + 1].w, h3, l3);
                *(uint4*)(buf + OA1 + xso[q]) = make_uint4(h0, h1, h2, h3);
                *(uint4*)(buf + OA2 + xso[q]) = make_uint4(l0, l1, l2, l3);
            }
#pragma unroll
            for (int i = 0; i < 4; i++) {
                *(uint4*)(buf + OB1 + wofs + i * 16) = wv0[i];
                *(uint4*)(buf + OB2 + wofs + i * 16) = wv1[i];
            }
            BAR_ARRIVE(1 + (c & 1));                 // signal buffer full
        }
    } else {
        // ================= CONSUMER warps (0-7) =================
        for (int c = 0; c < NCH; c++) {
            BAR_SYNC(1 + (c & 1));                   // wait buffer full
            const uint32_t bufb = sb + OFF_BUF + (uint32_t)(c & 1) * BUF_SZ;
#pragma unroll
            for (int ks = 0; ks < 4; ks++) {
                const uint32_t kx = (uint32_t)(ks << 5);
                uint32_t a1[4], a2[4], b1a[4], b1b[4], b2a[4], b2b[4];
                ldsm4(a1,  bufb + OA1 + (relA  ^ kx));
                ldsm4(a2,  bufb + OA2 + (relA  ^ kx));
                ldsm4(b1a, bufb + OB1 + (relB0 ^ kx));
                ldsm4(b1b, bufb + OB1 + (relB1 ^ kx));
                ldsm4(b2a, bufb + OB2 + (relB0 ^ kx));
                ldsm4(b2b, bufb + OB2 + (relB1 ^ kx));
#pragma unroll
                for (int t = 0; t < 4; t++) {
                    const uint32_t* p1 = (t < 2) ? &b1a[(t & 1) * 2] : &b1b[(t & 1) * 2];
                    const uint32_t* p2 = (t < 2) ? &b2a[(t & 1) * 2] : &b2b[(t & 1) * 2];
                    mma16816(acc[t], a1, p1);
                    mma16816(acc[t], a2, p1);
                    mma16816(acc[t], a1, p2);
                }
            }
            BAR_ARRIVE(3 + (c & 1));                 // signal buffer empty
        }
    }

    // ---------------- logits regs -> smem (consumers only) ----------------
    float (*ls)[LSTR] = reinterpret_cast<float(*)[LSTR]>(smem + OFF_BUF);
    if (wid < 8) {
        const int r0 = lid >> 2, c0 = 2 * (lid & 3);
#pragma unroll
        for (int t = 0; t < 4; t++) {
            const int mr = mbase + r0;
            const int nc = nbase + t * 8 + c0;
            *(float2*)&ls[mr][nc]     = make_float2(acc[t][0], acc[t][1]);
            *(float2*)&ls[mr + 8][nc] = make_float2(acc[t][2], acc[t][3]);
        }
    }
    __syncthreads();

    // ---------------- per-token epilogue + flagging ----------------
    if (tid < MT) {
        float mx = -INFINITY;
#pragma unroll 8
        for (int e = 0; e < E; e++) mx = fmaxf(mx, ls[tid][e]);
        float s = 0.f;
#pragma unroll 8
        for (int e = 0; e < E; e++) {
            float v = expf(ls[tid][e] - mx);
            s += v;
            ls[tid][e] = v;
        }
        const float inv = 1.f / s;
#pragma unroll 8
        for (int e = 0; e < E; e++) ls[tid][e] *= inv;

        ull used = 0ull;
        float pw[9]; int pi[9];
#pragma unroll
        for (int k = 0; k < 9; k++) {
            float bs = -1.f; int bi = 0;
            for (int e = 0; e < E; e++) {
                if ((used >> e) & 1ull) continue;
                float v = ls[tid][e];
                if (v > bs) { bs = v; bi = e; }
            }
            used |= (1ull << bi);
            pw[k] = bs; pi[k] = bi;
        }
        float ming = 1e30f;
#pragma unroll
        for (int k = 0; k < 8; k++) ming = fminf(ming, pw[k] - pw[k + 1]);

        if (ming < GAPTH) {
            int p = atomicAdd(&nflag, 1);
            flist[p] = tid;
        } else {
            float tsum = 0.f;
#pragma unroll
            for (int k = 0; k < KTOP; k++) tsum += pw[k];
            const float invw = 1.f / (tsum + 1e-20f);
            const size_t t = (size_t)m0 + tid;
#pragma unroll
            for (int k = 0; k < KTOP; k++) {
                out[t * KTOP + k]                       = (float)pi[k];
                out[(size_t)NTOK * KTOP + t * KTOP + k] = pw[k] * invw;
                atomicAdd(&cnt[pi[k]], 1);
            }
        }
    }
    __syncthreads();

    // ---------------- block-cooperative exact fixup ----------------
    float (*wst)[132] = reinterpret_cast<float(*)[132]>(smem + OFF_WST);
    const int fe = tid >> 2, fl = tid & 3;
    for (int f = 0; f < nflag; f++) {
        const int tl = flist[f];
        float accf = 0.f;
        for (int kb = 0; kb < H; kb += 128) {
            if (tid < 256) {
                const float* wsrc = w + (size_t)fe * H + kb;
#pragma unroll
                for (int j = 0; j < 8; j++) {
                    int s4 = j * 4 + fl;
                    float4 v = *(const float4*)(wsrc + s4 * 4);
                    *(float4*)&wst[fe][s4 * 4] = v;
                }
            }
            if (tid >= 64 && tid < 96) {
                float4 v = *(const float4*)(x + (size_t)(m0 + tl) * H + kb + (tid - 64) * 4);
                *(float4*)&xst[(tid - 64) * 4] = v;
            }
            __syncthreads();
            if (tid < E) {
#pragma unroll 8
                for (int kk = 0; kk < 128; kk++)
                    accf = fmaf(xst[kk], wst[tid][kk], accf);
            }
            __syncthreads();
        }
        if (tid < E) ls[tl][tid] = accf;
        __syncthreads();
        if (tid == 0) {
            float mx = -INFINITY;
            for (int e = 0; e < E; e++) mx = fmaxf(mx, ls[tl][e]);
            float s = 0.f;
            for (int e = 0; e < E; e++) {
                float v = expf(ls[tl][e] - mx);
                s += v;
                ls[tl][e] = v;
            }
            const float inv = 1.f / s;
            for (int e = 0; e < E; e++) ls[tl][e] *= inv;

            ull used = 0ull;
            float pw[KTOP]; int pi[KTOP];
            float tsum = 0.f;
            for (int k = 0; k < KTOP; k++) {
                float bs = -1.f; int bi = 0;
                for (int e = 0; e < E; e++) {
                    if ((used >> e) & 1ull) continue;
                    float v = ls[tl][e];
                    if (v > bs) { bs = v; bi = e; }
                }
                used |= (1ull << bi);
                pw[k] = bs; pi[k] = bi;
                tsum += bs;
            }
            const float invw = 1.f / (tsum + 1e-20f);
            const size_t t = (size_t)m0 + tl;
            for (int k = 0; k < KTOP; k++) {
                out[t * KTOP + k]                       = (float)pi[k];
                out[(size_t)NTOK * KTOP + t * KTOP + k] = pw[k] * invw;
                atomicAdd(&cnt[pi[k]], 1);
            }
        }
    }
    __syncthreads();

    // ---------------- per-block partials ----------------
    if (tid < E) {
        float s = 0.f;
        for (int t = 0; t < MT; t++) s += ls[t][tid];
        g_ssum[blockIdx.x][tid] = s;
        g_cnt [blockIdx.x][tid] = (float)cnt[tid];
    }
    __threadfence();
    __syncthreads();
    if (tid == 0) islast = (atomicAdd(&g_done, 1) == NBLK - 1);
    __syncthreads();

    // ---------------- fused aux reduction (last block) ----------------
    if (islast) {
        __threadfence();
        if (tid < 256) {
            const int b = tid >> 6;
            const int e = tid & 63;
            float ss = 0.f, cc = 0.f;
            const int base = b * (NBLK / BATCH);
#pragma unroll
            for (int blk = 0; blk < NBLK / BATCH; blk++) {
                ss += g_ssum[base + blk][e];
                cc += g_cnt [base + blk][e];
            }
            part[tid] = (cc * ((float)E / (float)(SEQ * KTOP))) * (ss * (1.f / (float)SEQ));
        }
        __syncthreads();
#pragma unroll
        for (int stride = 128; stride > 0; stride >>= 1) {
            if (tid < stride) part[tid] += part[tid + stride];
            __syncthreads();
        }
        if (tid == 0) {
            out[2 * (size_t)NTOK * KTOP] = part[0] * (0.1f / (float)BATCH);
            g_done = 0;
        }
    }
}

extern "C" void kernel_launch(void* const* d_in, const int* in_sizes, int n_in,
                              void* d_out, int out_size)
{
    const float* x = (const float*)d_in[0];   // hidden_states [4,4096,2048]
    const float* w = (const float*)d_in[1];   // weight        [64,2048]
    float* out = (float*)d_out;

    wsplit_kernel<<<64, 256>>>(w);
    cudaFuncSetAttribute(gate_kernel, cudaFuncAttributeMaxDynamicSharedMemorySize, SMEM_BYTES);
    gate_kernel<<<NBLK, NTHR, SMEM_BYTES>>>(x, w, out);
}

// round 13
// speedup vs baseline: 1.6298x; 1.6298x over previous
#include <cuda_runtime.h>
#include <cuda_bf16.h>
#include <cstdint>
#include <math.h>

#define H      2048
#define E      64
#define KTOP   8
#define NTOK   16384
#define SEQ    4096
#define BATCH  4
#define MT     32
#define NBLK   (NTOK / MT)     // 512 CTAs
#define NTHR   128
#define NCH    32              // K chunks of 64
#define GAPTH  8e-6f
#define LSTR   66

// dynamic smem: two 24KB buffers (Xhi 4K | Xlo 4K | Whi 8K | Wlo 8K)
#define OFF_BUF  1024
#define XA1      0
#define XA2      4096
#define WB1      8192
#define WB2      16384
#define BUF_SZ   24576
#define SMEM_BYTES (OFF_BUF + 2 * BUF_SZ)   // 50176

typedef unsigned long long ull;

__device__ float    g_ssum[NBLK][E];
__device__ float    g_cnt [NBLK][E];
__device__ int      g_done;
__device__ __align__(16) uint32_t g_wimg[NCH][2][2048];   // swizzled bf16 hi/lo W images

// ---------------- helpers ----------------
__device__ __forceinline__ uint32_t smem_u32(const void* p) {
    uint32_t a;
    asm("{ .reg .u64 t; cvta.to.shared.u64 t, %1; cvt.u32.u64 %0, t; }" : "=r"(a) : "l"(p));
    return a;
}
__device__ __forceinline__ uint32_t swz(uint32_t b) { return b ^ ((b >> 3) & 0x70); }

__device__ __forceinline__ void split2(float f0, float f1, uint32_t& hi, uint32_t& lo) {
    uint32_t h;
    asm("cvt.rn.bf16x2.f32 %0, %1, %2;" : "=r"(h) : "f"(f1), "f"(f0));
    float g0 = __uint_as_float(h << 16);
    float g1 = __uint_as_float(h & 0xFFFF0000u);
    asm("cvt.rn.bf16x2.f32 %0, %1, %2;" : "=r"(lo) : "f"(f1 - g1), "f"(f0 - g0));
    hi = h;
}
__device__ __forceinline__ void ldsm4(uint32_t* r, uint32_t addr) {
    asm volatile("ldmatrix.sync.aligned.m8n8.x4.shared.b16 {%0,%1,%2,%3}, [%4];"
        : "=r"(r[0]), "=r"(r[1]), "=r"(r[2]), "=r"(r[3]) : "r"(addr));
}
__device__ __forceinline__ void mma16816(float* d, const uint32_t* a, const uint32_t* b) {
    asm("mma.sync.aligned.m16n8k16.row.col.f32.bf16.bf16.f32 "
        "{%0,%1,%2,%3}, {%4,%5,%6,%7}, {%8,%9}, {%0,%1,%2,%3};"
        : "+f"(d[0]), "+f"(d[1]), "+f"(d[2]), "+f"(d[3])
        : "r"(a[0]), "r"(a[1]), "r"(a[2]), "r"(a[3]), "r"(b[0]), "r"(b[1]));
}
__device__ __forceinline__ void conv4(const float4 v, uint32_t* h, uint32_t* l) {
    split2(v.x, v.y, h[0], l[0]);
    split2(v.z, v.w, h[1], l[1]);
}
// ------------------------------------------

// Pre-split W into chunk-local swizzled bf16 hi/lo images.
__global__ __launch_bounds__(256, 1)
void wsplit_kernel(const float* __restrict__ w)
{
    int base = (blockIdx.x * 256 + threadIdx.x) * 4;
#pragma unroll
    for (int j = 0; j < 4; j++) {
        int pid = base + j;               // 0 .. 65535
        int r   = pid >> 10;
        int kp  = pid & 1023;
        int c   = kp >> 5;
        int kk2 = kp & 31;
        float f0 = w[(size_t)r * H + kp * 2];
        float f1 = w[(size_t)r * H + kp * 2 + 1];
        uint32_t hi, lo;
        split2(f0, f1, hi, lo);
        uint32_t off = swz((uint32_t)(r * 128 + kk2 * 4)) >> 2;
        g_wimg[c][0][off] = hi;
        g_wimg[c][1][off] = lo;
    }
}

__global__ __launch_bounds__(NTHR, 4)
void gate_kernel(const float* __restrict__ x,
                 const float* __restrict__ w,
                 float* __restrict__ out)
{
    extern __shared__ __align__(1024) char smem[];
    __shared__ __align__(16) float part[NTHR];
    __shared__ int cnt[E];
    __shared__ int nflag, flist[MT], islast;

    const uint32_t sb = smem_u32(smem);
    const int tid = threadIdx.x;
    const int wid = tid >> 5;
    const int lid = tid & 31;
    const int m0  = blockIdx.x * MT;

    if (tid == 0) nflag = 0;
    if (tid < E) cnt[tid] = 0;

    // ---------------- producer mapping (X tile 32x64 fp32) ----------------
    const int pr = tid >> 2;            // token row 0..31
    const int pq = tid & 3;             // 16-col quarter
    const float* xrow = x + (size_t)(m0 + pr) * H + pq * 16;
    const uint32_t sto0 = swz((uint32_t)(pr * 128 + pq * 32));
    const uint32_t sto1 = swz((uint32_t)(pr * 128 + pq * 32 + 16));

    // ---------------- consumer mapping (4 warps, 16x32 tiles) ----------------
    const int mbase = (wid & 1) * 16;
    const int nbase = (wid >> 1) * 32;
    const int arow = lid & 15;
    const int akh  = lid >> 4;
    const int brow = ((lid >> 4) * 8) + (lid & 7);
    const int bkh  = (lid >> 3) & 1;
    const uint32_t relA  = swz((uint32_t)((mbase + arow) * 128 + akh * 16));
    const uint32_t relB0 = swz((uint32_t)((nbase + brow) * 128 + bkh * 16));
    const uint32_t relB1 = swz((uint32_t)((nbase + 16 + brow) * 128 + bkh * 16));

    float acc[4][4];
#pragma unroll
    for (int t = 0; t < 4; t++)
#pragma unroll
        for (int r = 0; r < 4; r++) acc[t][r] = 0.f;

    float4 xv[4];
    uint4  wv0[4], wv1[4];
#pragma unroll
    for (int i = 0; i < 4; i++) xv[i] = *(const float4*)(xrow + i * 4);
#pragma unroll
    for (int i = 0; i < 4; i++) {
        wv0[i] = ((const uint4*)&g_wimg[0][0][0])[tid * 4 + i];
        wv1[i] = ((const uint4*)&g_wimg[0][1][0])[tid * 4 + i];
    }

    // ---------------- mainloop (R10-proven structure) ----------------
    for (int c = 0; c < NCH; c++) {
        char* buf = smem + OFF_BUF + (c & 1) * BUF_SZ;
        {
            uint32_t h[4], l[4];
            conv4(xv[0], h, l); conv4(xv[1], h + 2, l + 2);
            *(uint4*)(buf + XA1 + sto0) = make_uint4(h[0], h[1], h[2], h[3]);
            *(uint4*)(buf + XA2 + sto0) = make_uint4(l[0], l[1], l[2], l[3]);
            conv4(xv[2], h, l); conv4(xv[3], h + 2, l + 2);
            *(uint4*)(buf + XA1 + sto1) = make_uint4(h[0], h[1], h[2], h[3]);
            *(uint4*)(buf + XA2 + sto1) = make_uint4(l[0], l[1], l[2], l[3]);
#pragma unroll
            for (int i = 0; i < 4; i++) {
                *(uint4*)(buf + WB1 + tid * 64 + i * 16) = wv0[i];
                *(uint4*)(buf + WB2 + tid * 64 + i * 16) = wv1[i];
            }
        }
        if (c + 1 < NCH) {
            const float* xp = xrow + (c + 1) * 64;
#pragma unroll
            for (int i = 0; i < 4; i++) xv[i] = *(const float4*)(xp + i * 4);
#pragma unroll
            for (int i = 0; i < 4; i++) {
                wv0[i] = ((const uint4*)&g_wimg[c + 1][0][0])[tid * 4 + i];
                wv1[i] = ((const uint4*)&g_wimg[c + 1][1][0])[tid * 4 + i];
            }
        }
        __syncthreads();   // single barrier per chunk; double buffer protects

        const uint32_t bufb = sb + OFF_BUF + (uint32_t)(c & 1) * BUF_SZ;
#pragma unroll
        for (int ks = 0; ks < 4; ks++) {
            const uint32_t kx = (uint32_t)(ks << 5);
            uint32_t a1[4], a2[4], b1a[4], b1b[4], b2a[4], b2b[4];
            ldsm4(a1,  bufb + XA1 + (relA  ^ kx));
            ldsm4(a2,  bufb + XA2 + (relA  ^ kx));
            ldsm4(b1a, bufb + WB1 + (relB0 ^ kx));
            ldsm4(b1b, bufb + WB1 + (relB1 ^ kx));
            ldsm4(b2a, bufb + WB2 + (relB0 ^ kx));
            ldsm4(b2b, bufb + WB2 + (relB1 ^ kx));
#pragma unroll
            for (int t = 0; t < 4; t++) {
                const uint32_t* p1 = (t < 2) ? &b1a[(t & 1) * 2] : &b1b[(t & 1) * 2];
                const uint32_t* p2 = (t < 2) ? &b2a[(t & 1) * 2] : &b2b[(t & 1) * 2];
                mma16816(acc[t], a1, p1);
                mma16816(acc[t], a2, p1);
                mma16816(acc[t], a1, p2);
            }
        }
    }

    // ---------------- logits regs -> smem ----------------
    float (*ls)[LSTR] = reinterpret_cast<float(*)[LSTR]>(smem + OFF_BUF);
    {
        const int r0 = lid >> 2, c0 = 2 * (lid & 3);
#pragma unroll
        for (int t = 0; t < 4; t++) {
            const int mr = mbase + r0;
            const int nc = nbase + t * 8 + c0;
            *(float2*)&ls[mr][nc]     = make_float2(acc[t][0], acc[t][1]);
            *(float2*)&ls[mr + 8][nc] = make_float2(acc[t][2], acc[t][3]);
        }
    }
    __syncthreads();

    // ---------------- per-token epilogue + flagging ----------------
    if (tid < MT) {
        float mx = -INFINITY;
#pragma unroll 8
        for (int e = 0; e < E; e++) mx = fmaxf(mx, ls[tid][e]);
        float s = 0.f;
#pragma unroll 8
        for (int e = 0; e < E; e++) {
            float v = expf(ls[tid][e] - mx);
            s += v;
            ls[tid][e] = v;
        }
        const float inv = 1.f / s;
#pragma unroll 8
        for (int e = 0; e < E; e++) ls[tid][e] *= inv;

        ull used = 0ull;
        float pw[9]; int pi[9];
#pragma unroll
        for (int k = 0; k < 9; k++) {
            float bs = -1.f; int bi = 0;
            for (int e = 0; e < E; e++) {
                if ((used >> e) & 1ull) continue;
                float v = ls[tid][e];
                if (v > bs) { bs = v; bi = e; }
            }
            used |= (1ull << bi);
            pw[k] = bs; pi[k] = bi;
        }
        float ming = 1e30f;
#pragma unroll
        for (int k = 0; k < 8; k++) ming = fminf(ming, pw[k] - pw[k + 1]);

        if (ming < GAPTH) {
            int p = atomicAdd(&nflag, 1);
            flist[p] = tid;
        } else {
            float tsum = 0.f;
#pragma unroll
            for (int k = 0; k < KTOP; k++) tsum += pw[k];
            const float invw = 1.f / (tsum + 1e-20f);
            const size_t t = (size_t)m0 + tid;
#pragma unroll
            for (int k = 0; k < KTOP; k++) {
                out[t * KTOP + k]                       = (float)pi[k];
                out[(size_t)NTOK * KTOP + t * KTOP + k] = pw[k] * invw;
                atomicAdd(&cnt[pi[k]], 1);
            }
        }
    }
    __syncthreads();

    // ---------------- warp-parallel exact fixup (top-12 candidates) --------
    for (int i = wid; i < nflag; i += 4) {
        const int tl = flist[i];
        // approx top-12 candidates via warp argmax over ls probs
        float v0 = ls[tl][lid];
        float v1 = ls[tl][lid + 32];
        int myc = 0;
#pragma unroll
        for (int r = 0; r < 12; r++) {
            float bv; int bi;
            if (v0 >= v1) { bv = v0; bi = lid; } else { bv = v1; bi = lid + 32; }
#pragma unroll
            for (int off = 16; off; off >>= 1) {
                float ov = __shfl_xor_sync(0xffffffffu, bv, off);
                int   oi = __shfl_xor_sync(0xffffffffu, bi, off);
                if (ov > bv || (ov == bv && oi < bi)) { bv = ov; bi = oi; }
            }
            if (lid == r) myc = bi;
            if (bi == lid)      v0 = -1.f;
            if (bi == lid + 32) v1 = -1.f;
        }
        // lanes 0-11: exact ascending-k fp32 chain for candidate expert
        float ex = -INFINITY;
        if (lid < 12) {
            ex = 0.f;
            const float* xp = x + (size_t)(m0 + tl) * H;
            const float* wp = w + (size_t)myc * H;
            for (int k = 0; k < H; k += 8) {
                float4 xa = *(const float4*)(xp + k);
                float4 xb = *(const float4*)(xp + k + 4);
                float4 wa = *(const float4*)(wp + k);
                float4 wb = *(const float4*)(wp + k + 4);
                ex = fmaf(xa.x, wa.x, ex); ex = fmaf(xa.y, wa.y, ex);
                ex = fmaf(xa.z, wa.z, ex); ex = fmaf(xa.w, wa.w, ex);
                ex = fmaf(xb.x, wb.x, ex); ex = fmaf(xb.y, wb.y, ex);
                ex = fmaf(xb.z, wb.z, ex); ex = fmaf(xb.w, wb.w, ex);
            }
        }
        float exs[12]; int ids[12];
#pragma unroll
        for (int j = 0; j < 12; j++) {
            exs[j] = __shfl_sync(0xffffffffu, ex, j);
            ids[j] = __shfl_sync(0xffffffffu, myc, j);
        }
        if (lid == 0) {
            bool taken[12];
#pragma unroll
            for (int j = 0; j < 12; j++) taken[j] = false;
            float tsum = 0.f;
            float pw8[KTOP]; int pi8[KTOP];
            for (int k = 0; k < KTOP; k++) {
                int best = -1;
                for (int j = 0; j < 12; j++) {
                    if (taken[j]) continue;
                    if (best < 0 || exs[j] > exs[best] ||
                        (exs[j] == exs[best] && ids[j] < ids[best])) best = j;
                }
                taken[best] = true;
                pi8[k] = ids[best];
                pw8[k] = ls[tl][ids[best]];   // approx prob (4e-7 accuracy)
                tsum += pw8[k];
            }
            const float invw = 1.f / (tsum + 1e-20f);
            const size_t t = (size_t)m0 + tl;
            for (int k = 0; k < KTOP; k++) {
                out[t * KTOP + k]                       = (float)pi8[k];
                out[(size_t)NTOK * KTOP + t * KTOP + k] = pw8[k] * invw;
                atomicAdd(&cnt[pi8[k]], 1);
            }
        }
    }
    __syncthreads();

    // ---------------- per-block partials ----------------
    if (tid < E) {
        float s = 0.f;
        for (int t = 0; t < MT; t++) s += ls[t][tid];
        g_ssum[blockIdx.x][tid] = s;
        g_cnt [blockIdx.x][tid] = (float)cnt[tid];
    }
    __threadfence();
    __syncthreads();
    if (tid == 0) islast = (atomicAdd(&g_done, 1) == NBLK - 1);
    __syncthreads();

    // ---------------- fused aux reduction (last block) ----------------
    if (islast) {
        __threadfence();
        const int h = tid >> 6;          // batch half 0..1
        const int e = tid & 63;
        float accp = 0.f;
#pragma unroll
        for (int bb = 0; bb < 2; bb++) {
            const int b = h * 2 + bb;
            float ss = 0.f, cc = 0.f;
            const int base = b * (NBLK / BATCH);
#pragma unroll 4
            for (int blk = 0; blk < NBLK / BATCH; blk++) {
                ss += g_ssum[base + blk][e];
                cc += g_cnt [base + blk][e];
            }
            accp += (cc * ((float)E / (float)(SEQ * KTOP))) * (ss * (1.f / (float)SEQ));
        }
        part[tid] = accp;
        __syncthreads();
#pragma unroll
        for (int stride = 64; stride > 0; stride >>= 1) {
            if (tid < stride) part[tid] += part[tid + stride];
            __syncthreads();
        }
        if (tid == 0) {
            out[2 * (size_t)NTOK * KTOP] = part[0] * (0.1f / (float)BATCH);
            g_done = 0;
        }
    }
}

extern "C" void kernel_launch(void* const* d_in, const int* in_sizes, int n_in,
                              void* d_out, int out_size)
{
    const float* x = (const float*)d_in[0];   // hidden_states [4,4096,2048]
    const float* w = (const float*)d_in[1];   // weight        [64,2048]
    float* out = (float*)d_out;

    wsplit_kernel<<<64, 256>>>(w);
    cudaFuncSetAttribute(gate_kernel, cudaFuncAttributeMaxDynamicSharedMemorySize, SMEM_BYTES);
    gate_kernel<<<NBLK, NTHR, SMEM_BYTES>>>(x, w, out);
}

// round 14
// speedup vs baseline: 1.7072x; 1.0475x over previous
#include <cuda_runtime.h>
#include <cuda_bf16.h>
#include <cstdint>
#include <math.h>

#define H      2048
#define E      64
#define KTOP   8
#define NTOK   16384
#define SEQ    4096
#define BATCH  4
#define MT     64
#define NBLK   (NTOK / MT)     // 256 CTAs
#define NTHR   128
#define NCH    32              // K chunks of 64
#define GAPTH  8e-6f
#define LSTR   66

// dynamic smem: two 32KB buffers (Xhi 8K | Xlo 8K | Whi 8K | Wlo 8K)
#define OFF_BUF  1024
#define XA1      0
#define XA2      8192
#define WB1      16384
#define WB2      24576
#define BUF_SZ   32768
#define SMEM_BYTES (OFF_BUF + 2 * BUF_SZ)   // 66560

typedef unsigned long long ull;

__device__ float    g_ssum[NBLK][E];
__device__ float    g_cnt [NBLK][E];
__device__ int      g_done;
__device__ __align__(16) uint32_t g_wimg[NCH][2][2048];   // swizzled bf16 hi/lo W images

// ---------------- helpers ----------------
__device__ __forceinline__ uint32_t smem_u32(const void* p) {
    uint32_t a;
    asm("{ .reg .u64 t; cvta.to.shared.u64 t, %1; cvt.u32.u64 %0, t; }" : "=r"(a) : "l"(p));
    return a;
}
__device__ __forceinline__ uint32_t swz(uint32_t b) { return b ^ ((b >> 3) & 0x70); }

__device__ __forceinline__ void split2(float f0, float f1, uint32_t& hi, uint32_t& lo) {
    uint32_t h;
    asm("cvt.rn.bf16x2.f32 %0, %1, %2;" : "=r"(h) : "f"(f1), "f"(f0));
    float g0 = __uint_as_float(h << 16);
    float g1 = __uint_as_float(h & 0xFFFF0000u);
    asm("cvt.rn.bf16x2.f32 %0, %1, %2;" : "=r"(lo) : "f"(f1 - g1), "f"(f0 - g0));
    hi = h;
}
__device__ __forceinline__ void ldsm4(uint32_t* r, uint32_t addr) {
    asm volatile("ldmatrix.sync.aligned.m8n8.x4.shared.b16 {%0,%1,%2,%3}, [%4];"
        : "=r"(r[0]), "=r"(r[1]), "=r"(r[2]), "=r"(r[3]) : "r"(addr));
}
__device__ __forceinline__ void mma16816(float* d, const uint32_t* a, const uint32_t* b) {
    asm("mma.sync.aligned.m16n8k16.row.col.f32.bf16.bf16.f32 "
        "{%0,%1,%2,%3}, {%4,%5,%6,%7}, {%8,%9}, {%0,%1,%2,%3};"
        : "+f"(d[0]), "+f"(d[1]), "+f"(d[2]), "+f"(d[3])
        : "r"(a[0]), "r"(a[1]), "r"(a[2]), "r"(a[3]), "r"(b[0]), "r"(b[1]));
}
__device__ __forceinline__ void conv4(const float4 v, uint32_t* h, uint32_t* l) {
    split2(v.x, v.y, h[0], l[0]);
    split2(v.z, v.w, h[1], l[1]);
}
// ------------------------------------------

// Pre-split W into chunk-local swizzled bf16 hi/lo images.
__global__ __launch_bounds__(256, 1)
void wsplit_kernel(const float* __restrict__ w)
{
    int base = (blockIdx.x * 256 + threadIdx.x) * 4;
#pragma unroll
    for (int j = 0; j < 4; j++) {
        int pid = base + j;               // 0 .. 65535
        int r   = pid >> 10;
        int kp  = pid & 1023;
        int c   = kp >> 5;
        int kk2 = kp & 31;
        float f0 = w[(size_t)r * H + kp * 2];
        float f1 = w[(size_t)r * H + kp * 2 + 1];
        uint32_t hi, lo;
        split2(f0, f1, hi, lo);
        uint32_t off = swz((uint32_t)(r * 128 + kk2 * 4)) >> 2;
        g_wimg[c][0][off] = hi;
        g_wimg[c][1][off] = lo;
    }
}

__global__ __launch_bounds__(NTHR, 3)
void gate_kernel(const float* __restrict__ x,
                 const float* __restrict__ w,
                 float* __restrict__ out)
{
    extern __shared__ __align__(1024) char smem[];
    __shared__ __align__(16) float part[NTHR];
    __shared__ int cnt[E];
    __shared__ int nflag, flist[MT], islast;

    const uint32_t sb = smem_u32(smem);
    const int tid = threadIdx.x;
    const int wid = tid >> 5;
    const int lid = tid & 31;
    const int m0  = blockIdx.x * MT;

    if (tid == 0) nflag = 0;
    if (tid < E) cnt[tid] = 0;

    // ---------------- producer mapping (X tile 64x64 fp32) ----------------
    const int pr = tid >> 1;            // token row 0..63
    const int ph = tid & 1;             // 32-col half
    const float* xrow = x + (size_t)(m0 + pr) * H + ph * 32;
    uint32_t sto[2];
    sto[0] = swz((uint32_t)(pr * 128 + ph * 64));
    sto[1] = swz((uint32_t)(pr * 128 + ph * 64 + 16));
    uint32_t sto2[2];
    sto2[0] = swz((uint32_t)(pr * 128 + ph * 64 + 32));
    sto2[1] = swz((uint32_t)(pr * 128 + ph * 64 + 48));

    // ---------------- consumer mapping (4 warps, m32n32 tiles) -------------
    const int mbase = (wid & 1) * 32;
    const int nbase = (wid >> 1) * 32;
    const int arow = lid & 15;
    const int akh  = lid >> 4;
    const int brow = ((lid >> 4) * 8) + (lid & 7);
    const int bkh  = (lid >> 3) & 1;
    const uint32_t relA0 = swz((uint32_t)((mbase + arow) * 128 + akh * 16));
    const uint32_t relA1 = swz((uint32_t)((mbase + 16 + arow) * 128 + akh * 16));
    const uint32_t relB0 = swz((uint32_t)((nbase + brow) * 128 + bkh * 16));
    const uint32_t relB1 = swz((uint32_t)((nbase + 16 + brow) * 128 + bkh * 16));

    float acc[2][4][4];
#pragma unroll
    for (int m = 0; m < 2; m++)
#pragma unroll
        for (int t = 0; t < 4; t++)
#pragma unroll
            for (int r = 0; r < 4; r++) acc[m][t][r] = 0.f;

    float4 xv[8];
    uint4  wv0[4], wv1[4];
#pragma unroll
    for (int i = 0; i < 8; i++) xv[i] = *(const float4*)(xrow + i * 4);
#pragma unroll
    for (int i = 0; i < 4; i++) {
        wv0[i] = ((const uint4*)&g_wimg[0][0][0])[tid * 4 + i];
        wv1[i] = ((const uint4*)&g_wimg[0][1][0])[tid * 4 + i];
    }

    // ---------------- mainloop ----------------
    for (int c = 0; c < NCH; c++) {
        char* buf = smem + OFF_BUF + (c & 1) * BUF_SZ;
        {
            uint32_t h[4], l[4];
            conv4(xv[0], h, l); conv4(xv[1], h + 2, l + 2);
            *(uint4*)(buf + XA1 + sto[0]) = make_uint4(h[0], h[1], h[2], h[3]);
            *(uint4*)(buf + XA2 + sto[0]) = make_uint4(l[0], l[1], l[2], l[3]);
            conv4(xv[2], h, l); conv4(xv[3], h + 2, l + 2);
            *(uint4*)(buf + XA1 + sto[1]) = make_uint4(h[0], h[1], h[2], h[3]);
            *(uint4*)(buf + XA2 + sto[1]) = make_uint4(l[0], l[1], l[2], l[3]);
            conv4(xv[4], h, l); conv4(xv[5], h + 2, l + 2);
            *(uint4*)(buf + XA1 + sto2[0]) = make_uint4(h[0], h[1], h[2], h[3]);
            *(uint4*)(buf + XA2 + sto2[0]) = make_uint4(l[0], l[1], l[2], l[3]);
            conv4(xv[6], h, l); conv4(xv[7], h + 2, l + 2);
            *(uint4*)(buf + XA1 + sto2[1]) = make_uint4(h[0], h[1], h[2], h[3]);
            *(uint4*)(buf + XA2 + sto2[1]) = make_uint4(l[0], l[1], l[2], l[3]);
#pragma unroll
            for (int i = 0; i < 4; i++) {
                *(uint4*)(buf + WB1 + tid * 64 + i * 16) = wv0[i];
                *(uint4*)(buf + WB2 + tid * 64 + i * 16) = wv1[i];
            }
        }
        if (c + 1 < NCH) {
            const float* xp = xrow + (c + 1) * 64;
#pragma unroll
            for (int i = 0; i < 8; i++) xv[i] = *(const float4*)(xp + i * 4);
#pragma unroll
            for (int i = 0; i < 4; i++) {
                wv0[i] = ((const uint4*)&g_wimg[c + 1][0][0])[tid * 4 + i];
                wv1[i] = ((const uint4*)&g_wimg[c + 1][1][0])[tid * 4 + i];
            }
        }
        __syncthreads();

        const uint32_t bufb = sb + OFF_BUF + (uint32_t)(c & 1) * BUF_SZ;
#pragma unroll
        for (int ks = 0; ks < 4; ks++) {
            const uint32_t kx = (uint32_t)(ks << 5);
            uint32_t a1[2][4], a2[2][4], b1a[4], b1b[4], b2a[4], b2b[4];
            ldsm4(a1[0], bufb + XA1 + (relA0 ^ kx));
            ldsm4(a1[1], bufb + XA1 + (relA1 ^ kx));
            ldsm4(a2[0], bufb + XA2 + (relA0 ^ kx));
            ldsm4(a2[1], bufb + XA2 + (relA1 ^ kx));
            ldsm4(b1a, bufb + WB1 + (relB0 ^ kx));
            ldsm4(b1b, bufb + WB1 + (relB1 ^ kx));
            ldsm4(b2a, bufb + WB2 + (relB0 ^ kx));
            ldsm4(b2b, bufb + WB2 + (relB1 ^ kx));
#pragma unroll
            for (int m = 0; m < 2; m++)
#pragma unroll
                for (int t = 0; t < 4; t++) {
                    const uint32_t* p1 = (t < 2) ? &b1a[(t & 1) * 2] : &b1b[(t & 1) * 2];
                    const uint32_t* p2 = (t < 2) ? &b2a[(t & 1) * 2] : &b2b[(t & 1) * 2];
                    mma16816(acc[m][t], a1[m], p1);
                    mma16816(acc[m][t], a2[m], p1);
                    mma16816(acc[m][t], a1[m], p2);
                }
        }
    }

    // ---------------- logits regs -> smem ----------------
    float (*ls)[LSTR] = reinterpret_cast<float(*)[LSTR]>(smem + OFF_BUF);
    {
        const int r0 = lid >> 2, c0 = 2 * (lid & 3);
#pragma unroll
        for (int m = 0; m < 2; m++)
#pragma unroll
            for (int t = 0; t < 4; t++) {
                const int mr = mbase + m * 16 + r0;
                const int nc = nbase + t * 8 + c0;
                *(float2*)&ls[mr][nc]     = make_float2(acc[m][t][0], acc[m][t][1]);
                *(float2*)&ls[mr + 8][nc] = make_float2(acc[m][t][2], acc[m][t][3]);
            }
    }
    __syncthreads();

    // ---------------- per-token epilogue (single-pass top-9) + flagging ----
    if (tid < MT) {
        float mx = -INFINITY;
#pragma unroll 8
        for (int e = 0; e < E; e++) mx = fmaxf(mx, ls[tid][e]);
        float s = 0.f;
#pragma unroll 8
        for (int e = 0; e < E; e++) {
            float v = expf(ls[tid][e] - mx);
            s += v;
            ls[tid][e] = v;
        }
        const float inv = 1.f / s;

        // single-pass insertion top-9 (strict '>' == repeated-argmax ties)
        float pw[9]; int pi[9];
#pragma unroll
        for (int k = 0; k < 9; k++) { pw[k] = -1.f; pi[k] = 0; }
        for (int e = 0; e < E; e++) {
            float v = ls[tid][e] * inv;
            ls[tid][e] = v;
            if (v > pw[8]) {
                int j = 8;
#pragma unroll 8
                while (j > 0 && v > pw[j - 1]) {
                    pw[j] = pw[j - 1]; pi[j] = pi[j - 1]; j--;
                }
                pw[j] = v; pi[j] = e;
            }
        }
        float ming = 1e30f;
#pragma unroll
        for (int k = 0; k < 8; k++) ming = fminf(ming, pw[k] - pw[k + 1]);

        if (ming < GAPTH) {
            int p = atomicAdd(&nflag, 1);
            flist[p] = tid;
        } else {
            float tsum = 0.f;
#pragma unroll
            for (int k = 0; k < KTOP; k++) tsum += pw[k];
            const float invw = 1.f / (tsum + 1e-20f);
            const size_t t = (size_t)m0 + tid;
#pragma unroll
            for (int k = 0; k < KTOP; k++) {
                out[t * KTOP + k]                       = (float)pi[k];
                out[(size_t)NTOK * KTOP + t * KTOP + k] = pw[k] * invw;
                atomicAdd(&cnt[pi[k]], 1);
            }
        }
    }
    __syncthreads();

    // ---------------- warp-parallel exact fixup (top-12 candidates) --------
    for (int i = wid; i < nflag; i += 4) {
        const int tl = flist[i];
        float v0 = ls[tl][lid];
        float v1 = ls[tl][lid + 32];
        int myc = 0;
#pragma unroll
        for (int r = 0; r < 12; r++) {
            float bv; int bi;
            if (v0 >= v1) { bv = v0; bi = lid; } else { bv = v1; bi = lid + 32; }
#pragma unroll
            for (int off = 16; off; off >>= 1) {
                float ov = __shfl_xor_sync(0xffffffffu, bv, off);
                int   oi = __shfl_xor_sync(0xffffffffu, bi, off);
                if (ov > bv || (ov == bv && oi < bi)) { bv = ov; bi = oi; }
            }
            if (lid == r) myc = bi;
            if (bi == lid)      v0 = -1.f;
            if (bi == lid + 32) v1 = -1.f;
        }
        float ex = -INFINITY;
        if (lid < 12) {
            ex = 0.f;
            const float* xp = x + (size_t)(m0 + tl) * H;
            const float* wp = w + (size_t)myc * H;
            for (int k = 0; k < H; k += 8) {
                float4 xa = *(const float4*)(xp + k);
                float4 xb = *(const float4*)(xp + k + 4);
                float4 wa = *(const float4*)(wp + k);
                float4 wb = *(const float4*)(wp + k + 4);
                ex = fmaf(xa.x, wa.x, ex); ex = fmaf(xa.y, wa.y, ex);
                ex = fmaf(xa.z, wa.z, ex); ex = fmaf(xa.w, wa.w, ex);
                ex = fmaf(xb.x, wb.x, ex); ex = fmaf(xb.y, wb.y, ex);
                ex = fmaf(xb.z, wb.z, ex); ex = fmaf(xb.w, wb.w, ex);
            }
        }
        float exs[12]; int ids[12];
#pragma unroll
        for (int j = 0; j < 12; j++) {
            exs[j] = __shfl_sync(0xffffffffu, ex, j);
            ids[j] = __shfl_sync(0xffffffffu, myc, j);
        }
        if (lid == 0) {
            bool taken[12];
#pragma unroll
            for (int j = 0; j < 12; j++) taken[j] = false;
            float tsum = 0.f;
            float pw8[KTOP]; int pi8[KTOP];
            for (int k = 0; k < KTOP; k++) {
                int best = -1;
                for (int j = 0; j < 12; j++) {
                    if (taken[j]) continue;
                    if (best < 0 || exs[j] > exs[best] ||
                        (exs[j] == exs[best] && ids[j] < ids[best])) best = j;
                }
                taken[best] = true;
                pi8[k] = ids[best];
                pw8[k] = ls[tl][ids[best]];
                tsum += pw8[k];
            }
            const float invw = 1.f / (tsum + 1e-20f);
            const size_t t = (size_t)m0 + tl;
            for (int k = 0; k < KTOP; k++) {
                out[t * KTOP + k]                       = (float)pi8[k];
                out[(size_t)NTOK * KTOP + t * KTOP + k] = pw8[k] * invw;
                atomicAdd(&cnt[pi8[k]], 1);
            }
        }
    }
    __syncthreads();

    // ---------------- per-block partials ----------------
    if (tid < E) {
        float s = 0.f;
        for (int t = 0; t < MT; t++) s += ls[t][tid];
        g_ssum[blockIdx.x][tid] = s;
        g_cnt [blockIdx.x][tid] = (float)cnt[tid];
    }
    __threadfence();
    __syncthreads();
    if (tid == 0) islast = (atomicAdd(&g_done, 1) == NBLK - 1);
    __syncthreads();

    // ---------------- fused aux reduction (last block) ----------------
    if (islast) {
        __threadfence();
        const int h = tid >> 6;          // batch half 0..1
        const int e = tid & 63;
        float accp = 0.f;
#pragma unroll
        for (int bb = 0; bb < 2; bb++) {
            const int b = h * 2 + bb;
            float ss = 0.f, cc = 0.f;
            const int base = b * (NBLK / BATCH);
#pragma unroll 4
            for (int blk = 0; blk < NBLK / BATCH; blk++) {
                ss += g_ssum[base + blk][e];
                cc += g_cnt [base + blk][e];
            }
            accp += (cc * ((float)E / (float)(SEQ * KTOP))) * (ss * (1.f / (float)SEQ));
        }
        part[tid] = accp;
        __syncthreads();
#pragma unroll
        for (int stride = 64; stride > 0; stride >>= 1) {
            if (tid < stride) part[tid] += part[tid + stride];
            __syncthreads();
        }
        if (tid == 0) {
            out[2 * (size_t)NTOK * KTOP] = part[0] * (0.1f / (float)BATCH);
            g_done = 0;
        }
    }
}

extern "C" void kernel_launch(void* const* d_in, const int* in_sizes, int n_in,
                              void* d_out, int out_size)
{
    const float* x = (const float*)d_in[0];   // hidden_states [4,4096,2048]
    const float* w = (const float*)d_in[1];   // weight        [64,2048]
    float* out = (float*)d_out;

    wsplit_kernel<<<64, 256>>>(w);
    cudaFuncSetAttribute(gate_kernel, cudaFuncAttributeMaxDynamicSharedMemorySize, SMEM_BYTES);
    gate_kernel<<<NBLK, NTHR, SMEM_BYTES>>>(x, w, out);
}

// round 15
// speedup vs baseline: 2.4837x; 1.4549x over previous
#include <cuda_runtime.h>
#include <cuda_bf16.h>
#include <cstdint>
#include <math.h>

#define H      2048
#define E      64
#define KTOP   8
#define NTOK   16384
#define SEQ    4096
#define BATCH  4
#define MT     64
#define NBLK   (NTOK / MT)     // 256 CTAs
#define NTHR   256
#define NCH    32              // K chunks of 64
#define GAPTH  8e-6f
#define LSTR   66

// dynamic smem: two 32KB buffers (Xhi 8K | Xlo 8K | Whi 8K | Wlo 8K)
#define OFF_BUF  1024
#define XA1      0
#define XA2      8192
#define WB1      16384
#define WB2      24576
#define BUF_SZ   32768
#define SMEM_BYTES (OFF_BUF + 2 * BUF_SZ)   // 66560

typedef unsigned long long ull;

__device__ float    g_ssum[NBLK][E];
__device__ float    g_cnt [NBLK][E];
__device__ int      g_done;
__device__ __align__(16) uint32_t g_wimg[NCH][2][2048];   // swizzled bf16 hi/lo W images

// ---------------- helpers ----------------
__device__ __forceinline__ uint32_t smem_u32(const void* p) {
    uint32_t a;
    asm("{ .reg .u64 t; cvta.to.shared.u64 t, %1; cvt.u32.u64 %0, t; }" : "=r"(a) : "l"(p));
    return a;
}
__device__ __forceinline__ uint32_t swz(uint32_t b) { return b ^ ((b >> 3) & 0x70); }

__device__ __forceinline__ void split2(float f0, float f1, uint32_t& hi, uint32_t& lo) {
    uint32_t h;
    asm("cvt.rn.bf16x2.f32 %0, %1, %2;" : "=r"(h) : "f"(f1), "f"(f0));
    float g0 = __uint_as_float(h << 16);
    float g1 = __uint_as_float(h & 0xFFFF0000u);
    asm("cvt.rn.bf16x2.f32 %0, %1, %2;" : "=r"(lo) : "f"(f1 - g1), "f"(f0 - g0));
    hi = h;
}
__device__ __forceinline__ void ldsm4(uint32_t* r, uint32_t addr) {
    asm volatile("ldmatrix.sync.aligned.m8n8.x4.shared.b16 {%0,%1,%2,%3}, [%4];"
        : "=r"(r[0]), "=r"(r[1]), "=r"(r[2]), "=r"(r[3]) : "r"(addr));
}
__device__ __forceinline__ void mma16816(float* d, const uint32_t* a, const uint32_t* b) {
    asm("mma.sync.aligned.m16n8k16.row.col.f32.bf16.bf16.f32 "
        "{%0,%1,%2,%3}, {%4,%5,%6,%7}, {%8,%9}, {%0,%1,%2,%3};"
        : "+f"(d[0]), "+f"(d[1]), "+f"(d[2]), "+f"(d[3])
        : "r"(a[0]), "r"(a[1]), "r"(a[2]), "r"(a[3]), "r"(b[0]), "r"(b[1]));
}
__device__ __forceinline__ void conv4(const float4 v, uint32_t* h, uint32_t* l) {
    split2(v.x, v.y, h[0], l[0]);
    split2(v.z, v.w, h[1], l[1]);
}
// ------------------------------------------

// Pre-split W into chunk-local swizzled bf16 hi/lo images.
__global__ __launch_bounds__(256, 1)
void wsplit_kernel(const float* __restrict__ w)
{
    int base = (blockIdx.x * 256 + threadIdx.x) * 4;
#pragma unroll
    for (int j = 0; j < 4; j++) {
        int pid = base + j;               // 0 .. 65535
        int r   = pid >> 10;
        int kp  = pid & 1023;
        int c   = kp >> 5;
        int kk2 = kp & 31;
        float f0 = w[(size_t)r * H + kp * 2];
        float f1 = w[(size_t)r * H + kp * 2 + 1];
        uint32_t hi, lo;
        split2(f0, f1, hi, lo);
        uint32_t off = swz((uint32_t)(r * 128 + kk2 * 4)) >> 2;
        g_wimg[c][0][off] = hi;
        g_wimg[c][1][off] = lo;
    }
}

__global__ __launch_bounds__(NTHR, 2)
void gate_kernel(const float* __restrict__ x,
                 const float* __restrict__ w,
                 float* __restrict__ out)
{
    extern __shared__ __align__(1024) char smem[];
    __shared__ __align__(16) float part[NTHR];
    __shared__ int cnt[E];
    __shared__ int nflag, flist[MT], islast;

    const uint32_t sb = smem_u32(smem);
    const int tid = threadIdx.x;
    const int wid = tid >> 5;
    const int lid = tid & 31;
    const int m0  = blockIdx.x * MT;

    if (tid == 0) nflag = 0;
    if (tid < E) cnt[tid] = 0;

    // ---------------- producer mapping (X tile 64x64 fp32) ----------------
    const int pr = tid >> 2;            // token row 0..63
    const int pq = tid & 3;             // 16-col quarter
    const float* xrow = x + (size_t)(m0 + pr) * H + pq * 16;
    const uint32_t sto0 = swz((uint32_t)(pr * 128 + pq * 32));
    const uint32_t sto1 = swz((uint32_t)(pr * 128 + pq * 32 + 16));

    // ---------------- consumer mapping (8 warps, m16n32 tiles) -------------
    const int mbase = (wid & 3) * 16;
    const int nbase = (wid >> 2) * 32;
    const int arow = lid & 15;
    const int akh  = lid >> 4;
    const int brow = ((lid >> 4) * 8) + (lid & 7);
    const int bkh  = (lid >> 3) & 1;
    const uint32_t relA  = swz((uint32_t)((mbase + arow) * 128 + akh * 16));
    const uint32_t relB0 = swz((uint32_t)((nbase + brow) * 128 + bkh * 16));
    const uint32_t relB1 = swz((uint32_t)((nbase + 16 + brow) * 128 + bkh * 16));

    float acc[4][4];
#pragma unroll
    for (int t = 0; t < 4; t++)
#pragma unroll
        for (int r = 0; r < 4; r++) acc[t][r] = 0.f;

    float4 xv[4];
    uint4  wv0[2], wv1[2];
#pragma unroll
    for (int i = 0; i < 4; i++) xv[i] = *(const float4*)(xrow + i * 4);
#pragma unroll
    for (int i = 0; i < 2; i++) {
        wv0[i] = ((const uint4*)&g_wimg[0][0][0])[tid * 2 + i];
        wv1[i] = ((const uint4*)&g_wimg[0][1][0])[tid * 2 + i];
    }

    // ---------------- mainloop ----------------
    for (int c = 0; c < NCH; c++) {
        char* buf = smem + OFF_BUF + (c & 1) * BUF_SZ;
        {
            uint32_t h[4], l[4];
            conv4(xv[0], h, l); conv4(xv[1], h + 2, l + 2);
            *(uint4*)(buf + XA1 + sto0) = make_uint4(h[0], h[1], h[2], h[3]);
            *(uint4*)(buf + XA2 + sto0) = make_uint4(l[0], l[1], l[2], l[3]);
            conv4(xv[2], h, l); conv4(xv[3], h + 2, l + 2);
            *(uint4*)(buf + XA1 + sto1) = make_uint4(h[0], h[1], h[2], h[3]);
            *(uint4*)(buf + XA2 + sto1) = make_uint4(l[0], l[1], l[2], l[3]);
            // W pass-through (pre-split, pre-swizzled)
            *(uint4*)(buf + WB1 + tid * 32)      = wv0[0];
            *(uint4*)(buf + WB1 + tid * 32 + 16) = wv0[1];
            *(uint4*)(buf + WB2 + tid * 32)      = wv1[0];
            *(uint4*)(buf + WB2 + tid * 32 + 16) = wv1[1];
        }
        if (c + 1 < NCH) {
            const float* xp = xrow + (c + 1) * 64;
#pragma unroll
            for (int i = 0; i < 4; i++) xv[i] = *(const float4*)(xp + i * 4);
#pragma unroll
            for (int i = 0; i < 2; i++) {
                wv0[i] = ((const uint4*)&g_wimg[c + 1][0][0])[tid * 2 + i];
                wv1[i] = ((const uint4*)&g_wimg[c + 1][1][0])[tid * 2 + i];
            }
        }
        __syncthreads();

        const uint32_t bufb = sb + OFF_BUF + (uint32_t)(c & 1) * BUF_SZ;
#pragma unroll
        for (int ks = 0; ks < 4; ks++) {
            const uint32_t kx = (uint32_t)(ks << 5);
            uint32_t a1[4], a2[4], b1a[4], b1b[4], b2a[4], b2b[4];
            ldsm4(a1,  bufb + XA1 + (relA  ^ kx));
            ldsm4(a2,  bufb + XA2 + (relA  ^ kx));
            ldsm4(b1a, bufb + WB1 + (relB0 ^ kx));
            ldsm4(b1b, bufb + WB1 + (relB1 ^ kx));
            ldsm4(b2a, bufb + WB2 + (relB0 ^ kx));
            ldsm4(b2b, bufb + WB2 + (relB1 ^ kx));
#pragma unroll
            for (int t = 0; t < 4; t++) {
                const uint32_t* p1 = (t < 2) ? &b1a[(t & 1) * 2] : &b1b[(t & 1) * 2];
                const uint32_t* p2 = (t < 2) ? &b2a[(t & 1) * 2] : &b2b[(t & 1) * 2];
                mma16816(acc[t], a1, p1);
                mma16816(acc[t], a2, p1);
                mma16816(acc[t], a1, p2);
            }
        }
    }

    // ---------------- logits regs -> smem ----------------
    float (*ls)[LSTR] = reinterpret_cast<float(*)[LSTR]>(smem + OFF_BUF);
    {
        const int r0 = lid >> 2, c0 = 2 * (lid & 3);
#pragma unroll
        for (int t = 0; t < 4; t++) {
            const int mr = mbase + r0;
            const int nc = nbase + t * 8 + c0;
            *(float2*)&ls[mr][nc]     = make_float2(acc[t][0], acc[t][1]);
            *(float2*)&ls[mr + 8][nc] = make_float2(acc[t][2], acc[t][3]);
        }
    }
    __syncthreads();

    // ---------------- per-token epilogue (single-pass top-9) + flagging ----
    if (tid < MT) {
        float mx = -INFINITY;
#pragma unroll 8
        for (int e = 0; e < E; e++) mx = fmaxf(mx, ls[tid][e]);
        float s = 0.f;
#pragma unroll 8
        for (int e = 0; e < E; e++) {
            float v = expf(ls[tid][e] - mx);
            s += v;
            ls[tid][e] = v;
        }
        const float inv = 1.f / s;

        float pw[9]; int pi[9];
#pragma unroll
        for (int k = 0; k < 9; k++) { pw[k] = -1.f; pi[k] = 0; }
        for (int e = 0; e < E; e++) {
            float v = ls[tid][e] * inv;
            ls[tid][e] = v;
            if (v > pw[8]) {
                int j = 8;
#pragma unroll 8
                while (j > 0 && v > pw[j - 1]) {
                    pw[j] = pw[j - 1]; pi[j] = pi[j - 1]; j--;
                }
                pw[j] = v; pi[j] = e;
            }
        }
        float ming = 1e30f;
#pragma unroll
        for (int k = 0; k < 8; k++) ming = fminf(ming, pw[k] - pw[k + 1]);

        if (ming < GAPTH) {
            int p = atomicAdd(&nflag, 1);
            flist[p] = tid;
        } else {
            float tsum = 0.f;
#pragma unroll
            for (int k = 0; k < KTOP; k++) tsum += pw[k];
            const float invw = 1.f / (tsum + 1e-20f);
            const size_t t = (size_t)m0 + tid;
#pragma unroll
            for (int k = 0; k < KTOP; k++) {
                out[t * KTOP + k]                       = (float)pi[k];
                out[(size_t)NTOK * KTOP + t * KTOP + k] = pw[k] * invw;
                atomicAdd(&cnt[pi[k]], 1);
            }
        }
    }
    __syncthreads();

    // ---------------- warp-parallel exact fixup (top-12 candidates) --------
    for (int i = wid; i < nflag; i += 8) {
        const int tl = flist[i];
        float v0 = ls[tl][lid];
        float v1 = ls[tl][lid + 32];
        int myc = 0;
#pragma unroll
        for (int r = 0; r < 12; r++) {
            float bv; int bi;
            if (v0 >= v1) { bv = v0; bi = lid; } else { bv = v1; bi = lid + 32; }
#pragma unroll
            for (int off = 16; off; off >>= 1) {
                float ov = __shfl_xor_sync(0xffffffffu, bv, off);
                int   oi = __shfl_xor_sync(0xffffffffu, bi, off);
                if (ov > bv || (ov == bv && oi < bi)) { bv = ov; bi = oi; }
            }
            if (lid == r) myc = bi;
            if (bi == lid)      v0 = -1.f;
            if (bi == lid + 32) v1 = -1.f;
        }
        float ex = -INFINITY;
        if (lid < 12) {
            ex = 0.f;
            const float* xp = x + (size_t)(m0 + tl) * H;
            const float* wp = w + (size_t)myc * H;
            for (int k = 0; k < H; k += 8) {
                float4 xa = *(const float4*)(xp + k);
                float4 xb = *(const float4*)(xp + k + 4);
                float4 wa = *(const float4*)(wp + k);
                float4 wb = *(const float4*)(wp + k + 4);
                ex = fmaf(xa.x, wa.x, ex); ex = fmaf(xa.y, wa.y, ex);
                ex = fmaf(xa.z, wa.z, ex); ex = fmaf(xa.w, wa.w, ex);
                ex = fmaf(xb.x, wb.x, ex); ex = fmaf(xb.y, wb.y, ex);
                ex = fmaf(xb.z, wb.z, ex); ex = fmaf(xb.w, wb.w, ex);
            }
        }
        float exs[12]; int ids[12];
#pragma unroll
        for (int j = 0; j < 12; j++) {
            exs[j] = __shfl_sync(0xffffffffu, ex, j);
            ids[j] = __shfl_sync(0xffffffffu, myc, j);
        }
        if (lid == 0) {
            bool taken[12];
#pragma unroll
            for (int j = 0; j < 12; j++) taken[j] = false;
            float tsum = 0.f;
            float pw8[KTOP]; int pi8[KTOP];
            for (int k = 0; k < KTOP; k++) {
                int best = -1;
                for (int j = 0; j < 12; j++) {
                    if (taken[j]) continue;
                    if (best < 0 || exs[j] > exs[best] ||
                        (exs[j] == exs[best] && ids[j] < ids[best])) best = j;
                }
                taken[best] = true;
                pi8[k] = ids[best];
                pw8[k] = ls[tl][ids[best]];
                tsum += pw8[k];
            }
            const float invw = 1.f / (tsum + 1e-20f);
            const size_t t = (size_t)m0 + tl;
            for (int k = 0; k < KTOP; k++) {
                out[t * KTOP + k]                       = (float)pi8[k];
                out[(size_t)NTOK * KTOP + t * KTOP + k] = pw8[k] * invw;
                atomicAdd(&cnt[pi8[k]], 1);
            }
        }
    }
    __syncthreads();

    // ---------------- per-block partials ----------------
    if (tid < E) {
        float s = 0.f;
        for (int t = 0; t < MT; t++) s += ls[t][tid];
        g_ssum[blockIdx.x][tid] = s;
        g_cnt [blockIdx.x][tid] = (float)cnt[tid];
    }
    __threadfence();
    __syncthreads();
    if (tid == 0) islast = (atomicAdd(&g_done, 1) == NBLK - 1);
    __syncthreads();

    // ---------------- fused aux reduction (last block) ----------------
    if (islast) {
        __threadfence();
        const int b = tid >> 6;
        const int e = tid & 63;
        float ss = 0.f, cc = 0.f;
        const int base = b * (NBLK / BATCH);
#pragma unroll
        for (int blk = 0; blk < NBLK / BATCH; blk++) {
            ss += g_ssum[base + blk][e];
            cc += g_cnt [base + blk][e];
        }
        part[tid] = (cc * ((float)E / (float)(SEQ * KTOP))) * (ss * (1.f / (float)SEQ));
        __syncthreads();
#pragma unroll
        for (int stride = 128; stride > 0; stride >>= 1) {
            if (tid < stride) part[tid] += part[tid + stride];
            __syncthreads();
        }
        if (tid == 0) {
            out[2 * (size_t)NTOK * KTOP] = part[0] * (0.1f / (float)BATCH);
            g_done = 0;
        }
    }
}

extern "C" void kernel_launch(void* const* d_in, const int* in_sizes, int n_in,
                              void* d_out, int out_size)
{
    const float* x = (const float*)d_in[0];   // hidden_states [4,4096,2048]
    const float* w = (const float*)d_in[1];   // weight        [64,2048]
    float* out = (float*)d_out;

    wsplit_kernel<<<64, 256>>>(w);
    cudaFuncSetAttribute(gate_kernel, cudaFuncAttributeMaxDynamicSharedMemorySize, SMEM_BYTES);
    gate_kernel<<<NBLK, NTHR, SMEM_BYTES>>>(x, w, out);
}

// round 16
// speedup vs baseline: 2.6348x; 1.0608x over previous
#include <cuda_runtime.h>
#include <cuda_bf16.h>
#include <cstdint>
#include <math.h>

#define H      2048
#define E      64
#define KTOP   8
#define NTOK   16384
#define SEQ    4096
#define BATCH  4
#define MT     64
#define NBLK   (NTOK / MT)     // 256 CTAs
#define NTHR   256
#define NCH    32              // K chunks of 64
#define GAPTH  8e-6f
#define LSTR   66

// dynamic smem: two 32KB buffers (Xhi 8K | Xlo 8K | Whi 8K | Wlo 8K)
#define OFF_BUF  1024
#define XA1      0
#define XA2      8192
#define WB1      16384
#define WB2      24576
#define BUF_SZ   32768
#define SMEM_BYTES (OFF_BUF + 2 * BUF_SZ)   // 66560

typedef unsigned long long ull;

__device__ float    g_ssum[NBLK][E];
__device__ float    g_cnt [NBLK][E];
__device__ int      g_done;
__device__ __align__(16) uint32_t g_wimg[NCH][2][2048];   // swizzled bf16 hi/lo W images

// ---------------- helpers ----------------
__device__ __forceinline__ uint32_t smem_u32(const void* p) {
    uint32_t a;
    asm("{ .reg .u64 t; cvta.to.shared.u64 t, %1; cvt.u32.u64 %0, t; }" : "=r"(a) : "l"(p));
    return a;
}
__device__ __forceinline__ uint32_t swz(uint32_t b) { return b ^ ((b >> 3) & 0x70); }

__device__ __forceinline__ void split2(float f0, float f1, uint32_t& hi, uint32_t& lo) {
    uint32_t h;
    asm("cvt.rn.bf16x2.f32 %0, %1, %2;" : "=r"(h) : "f"(f1), "f"(f0));
    float g0 = __uint_as_float(h << 16);
    float g1 = __uint_as_float(h & 0xFFFF0000u);
    asm("cvt.rn.bf16x2.f32 %0, %1, %2;" : "=r"(lo) : "f"(f1 - g1), "f"(f0 - g0));
    hi = h;
}
__device__ __forceinline__ void ldsm4(uint32_t* r, uint32_t addr) {
    asm volatile("ldmatrix.sync.aligned.m8n8.x4.shared.b16 {%0,%1,%2,%3}, [%4];"
        : "=r"(r[0]), "=r"(r[1]), "=r"(r[2]), "=r"(r[3]) : "r"(addr));
}
__device__ __forceinline__ void mma16816(float* d, const uint32_t* a, const uint32_t* b) {
    asm("mma.sync.aligned.m16n8k16.row.col.f32.bf16.bf16.f32 "
        "{%0,%1,%2,%3}, {%4,%5,%6,%7}, {%8,%9}, {%0,%1,%2,%3};"
        : "+f"(d[0]), "+f"(d[1]), "+f"(d[2]), "+f"(d[3])
        : "r"(a[0]), "r"(a[1]), "r"(a[2]), "r"(a[3]), "r"(b[0]), "r"(b[1]));
}
__device__ __forceinline__ void conv4(const float4 v, uint32_t* h, uint32_t* l) {
    split2(v.x, v.y, h[0], l[0]);
    split2(v.z, v.w, h[1], l[1]);
}
// ------------------------------------------

// Pre-split W into chunk-local swizzled bf16 hi/lo images.
__global__ __launch_bounds__(256, 1)
void wsplit_kernel(const float* __restrict__ w)
{
    int base = (blockIdx.x * 256 + threadIdx.x) * 4;
#pragma unroll
    for (int j = 0; j < 4; j++) {
        int pid = base + j;               // 0 .. 65535
        int r   = pid >> 10;
        int kp  = pid & 1023;
        int c   = kp >> 5;
        int kk2 = kp & 31;
        float f0 = w[(size_t)r * H + kp * 2];
        float f1 = w[(size_t)r * H + kp * 2 + 1];
        uint32_t hi, lo;
        split2(f0, f1, hi, lo);
        uint32_t off = swz((uint32_t)(r * 128 + kk2 * 4)) >> 2;
        g_wimg[c][0][off] = hi;
        g_wimg[c][1][off] = lo;
    }
}

__global__ __launch_bounds__(NTHR, 2)
void gate_kernel(const float* __restrict__ x,
                 const float* __restrict__ w,
                 float* __restrict__ out)
{
    extern __shared__ __align__(1024) char smem[];
    __shared__ __align__(16) float part[NTHR];
    __shared__ int cnt[E];
    __shared__ int nflag, flist[MT], islast;

    const uint32_t sb = smem_u32(smem);
    const int tid = threadIdx.x;
    const int wid = tid >> 5;
    const int lid = tid & 31;
    const int m0  = blockIdx.x * MT;

    if (tid == 0) nflag = 0;
    if (tid < E) cnt[tid] = 0;

    // ---------------- producer mapping (X tile 64x64 fp32) ----------------
    const int pr = tid >> 2;            // token row 0..63
    const int pq = tid & 3;             // 16-col quarter
    const float* xrow = x + (size_t)(m0 + pr) * H + pq * 16;
    const uint32_t sto0 = swz((uint32_t)(pr * 128 + pq * 32));
    const uint32_t sto1 = swz((uint32_t)(pr * 128 + pq * 32 + 16));

    // ------------- consumer mapping (m32 x n32 x K-half per warp) ----------
    const int mbase = (wid & 1) * 32;
    const int nbase = ((wid >> 1) & 1) * 32;
    const int khalf = wid >> 2;         // 0: ks 0-1, 1: ks 2-3
    const int arow = lid & 15;
    const int akh  = lid >> 4;
    const int brow = ((lid >> 4) * 8) + (lid & 7);
    const int bkh  = (lid >> 3) & 1;
    const uint32_t relA0 = swz((uint32_t)((mbase + arow) * 128 + akh * 16));
    const uint32_t relA1 = swz((uint32_t)((mbase + 16 + arow) * 128 + akh * 16));
    const uint32_t relB0 = swz((uint32_t)((nbase + brow) * 128 + bkh * 16));
    const uint32_t relB1 = swz((uint32_t)((nbase + 16 + brow) * 128 + bkh * 16));

    float acc[2][4][4];
#pragma unroll
    for (int m = 0; m < 2; m++)
#pragma unroll
        for (int t = 0; t < 4; t++)
#pragma unroll
            for (int r = 0; r < 4; r++) acc[m][t][r] = 0.f;

    float4 xv[4];
    uint4  wv0[2], wv1[2];
#pragma unroll
    for (int i = 0; i < 4; i++) xv[i] = *(const float4*)(xrow + i * 4);
#pragma unroll
    for (int i = 0; i < 2; i++) {
        wv0[i] = ((const uint4*)&g_wimg[0][0][0])[tid * 2 + i];
        wv1[i] = ((const uint4*)&g_wimg[0][1][0])[tid * 2 + i];
    }

    // ---------------- mainloop ----------------
    for (int c = 0; c < NCH; c++) {
        char* buf = smem + OFF_BUF + (c & 1) * BUF_SZ;
        {
            uint32_t h[4], l[4];
            conv4(xv[0], h, l); conv4(xv[1], h + 2, l + 2);
            *(uint4*)(buf + XA1 + sto0) = make_uint4(h[0], h[1], h[2], h[3]);
            *(uint4*)(buf + XA2 + sto0) = make_uint4(l[0], l[1], l[2], l[3]);
            conv4(xv[2], h, l); conv4(xv[3], h + 2, l + 2);
            *(uint4*)(buf + XA1 + sto1) = make_uint4(h[0], h[1], h[2], h[3]);
            *(uint4*)(buf + XA2 + sto1) = make_uint4(l[0], l[1], l[2], l[3]);
            // W pass-through (pre-split, pre-swizzled)
            *(uint4*)(buf + WB1 + tid * 32)      = wv0[0];
            *(uint4*)(buf + WB1 + tid * 32 + 16) = wv0[1];
            *(uint4*)(buf + WB2 + tid * 32)      = wv1[0];
            *(uint4*)(buf + WB2 + tid * 32 + 16) = wv1[1];
        }
        if (c + 1 < NCH) {
            const float* xp = xrow + (c + 1) * 64;
#pragma unroll
            for (int i = 0; i < 4; i++) xv[i] = *(const float4*)(xp + i * 4);
#pragma unroll
            for (int i = 0; i < 2; i++) {
                wv0[i] = ((const uint4*)&g_wimg[c + 1][0][0])[tid * 2 + i];
                wv1[i] = ((const uint4*)&g_wimg[c + 1][1][0])[tid * 2 + i];
            }
        }
        __syncthreads();

        const uint32_t bufb = sb + OFF_BUF + (uint32_t)(c & 1) * BUF_SZ;
#pragma unroll
        for (int kss = 0; kss < 2; kss++) {
            const uint32_t kx = (uint32_t)((khalf * 2 + kss) << 5);
            uint32_t a1[2][4], a2[2][4], b1a[4], b1b[4], b2a[4], b2b[4];
            ldsm4(a1[0], bufb + XA1 + (relA0 ^ kx));
            ldsm4(a1[1], bufb + XA1 + (relA1 ^ kx));
            ldsm4(a2[0], bufb + XA2 + (relA0 ^ kx));
            ldsm4(a2[1], bufb + XA2 + (relA1 ^ kx));
            ldsm4(b1a, bufb + WB1 + (relB0 ^ kx));
            ldsm4(b1b, bufb + WB1 + (relB1 ^ kx));
            ldsm4(b2a, bufb + WB2 + (relB0 ^ kx));
            ldsm4(b2b, bufb + WB2 + (relB1 ^ kx));
#pragma unroll
            for (int m = 0; m < 2; m++)
#pragma unroll
                for (int t = 0; t < 4; t++) {
                    const uint32_t* p1 = (t < 2) ? &b1a[(t & 1) * 2] : &b1b[(t & 1) * 2];
                    const uint32_t* p2 = (t < 2) ? &b2a[(t & 1) * 2] : &b2b[(t & 1) * 2];
                    mma16816(acc[m][t], a1[m], p1);
                    mma16816(acc[m][t], a2[m], p1);
                    mma16816(acc[m][t], a1[m], p2);
                }
        }
    }

    // ---------------- logits regs -> smem (two-phase K-half merge) ---------
    float (*ls)[LSTR] = reinterpret_cast<float(*)[LSTR]>(smem + OFF_BUF);
    const int r0 = lid >> 2, c0 = 2 * (lid & 3);
    __syncthreads();
    if (khalf == 0) {
#pragma unroll
        for (int m = 0; m < 2; m++)
#pragma unroll
            for (int t = 0; t < 4; t++) {
                const int mr = mbase + m * 16 + r0;
                const int nc = nbase + t * 8 + c0;
                *(float2*)&ls[mr][nc]     = make_float2(acc[m][t][0], acc[m][t][1]);
                *(float2*)&ls[mr + 8][nc] = make_float2(acc[m][t][2], acc[m][t][3]);
            }
    }
    __syncthreads();
    if (khalf == 1) {
#pragma unroll
        for (int m = 0; m < 2; m++)
#pragma unroll
            for (int t = 0; t < 4; t++) {
                const int mr = mbase + m * 16 + r0;
                const int nc = nbase + t * 8 + c0;
                float2 p0 = *(const float2*)&ls[mr][nc];
                float2 p1v = *(const float2*)&ls[mr + 8][nc];
                *(float2*)&ls[mr][nc]     = make_float2(p0.x + acc[m][t][0], p0.y + acc[m][t][1]);
                *(float2*)&ls[mr + 8][nc] = make_float2(p1v.x + acc[m][t][2], p1v.y + acc[m][t][3]);
            }
    }
    __syncthreads();

    // ---------------- per-token epilogue (single-pass top-9) + flagging ----
    if (tid < MT) {
        float mx = -INFINITY;
#pragma unroll 8
        for (int e = 0; e < E; e++) mx = fmaxf(mx, ls[tid][e]);
        float s = 0.f;
#pragma unroll 8
        for (int e = 0; e < E; e++) {
            float v = expf(ls[tid][e] - mx);
            s += v;
            ls[tid][e] = v;
        }
        const float inv = 1.f / s;

        float pw[9]; int pi[9];
#pragma unroll
        for (int k = 0; k < 9; k++) { pw[k] = -1.f; pi[k] = 0; }
        for (int e = 0; e < E; e++) {
            float v = ls[tid][e] * inv;
            ls[tid][e] = v;
            if (v > pw[8]) {
                int j = 8;
#pragma unroll 8
                while (j > 0 && v > pw[j - 1]) {
                    pw[j] = pw[j - 1]; pi[j] = pi[j - 1]; j--;
                }
                pw[j] = v; pi[j] = e;
            }
        }
        float ming = 1e30f;
#pragma unroll
        for (int k = 0; k < 8; k++) ming = fminf(ming, pw[k] - pw[k + 1]);

        if (ming < GAPTH) {
            int p = atomicAdd(&nflag, 1);
            flist[p] = tid;
        } else {
            float tsum = 0.f;
#pragma unroll
            for (int k = 0; k < KTOP; k++) tsum += pw[k];
            const float invw = 1.f / (tsum + 1e-20f);
            const size_t t = (size_t)m0 + tid;
#pragma unroll
            for (int k = 0; k < KTOP; k++) {
                out[t * KTOP + k]                       = (float)pi[k];
                out[(size_t)NTOK * KTOP + t * KTOP + k] = pw[k] * invw;
                atomicAdd(&cnt[pi[k]], 1);
            }
        }
    }
    __syncthreads();

    // ---------------- warp-parallel exact fixup (top-12 candidates) --------
    for (int i = wid; i < nflag; i += 8) {
        const int tl = flist[i];
        float v0 = ls[tl][lid];
        float v1 = ls[tl][lid + 32];
        int myc = 0;
#pragma unroll
        for (int r = 0; r < 12; r++) {
            float bv; int bi;
            if (v0 >= v1) { bv = v0; bi = lid; } else { bv = v1; bi = lid + 32; }
#pragma unroll
            for (int off = 16; off; off >>= 1) {
                float ov = __shfl_xor_sync(0xffffffffu, bv, off);
                int   oi = __shfl_xor_sync(0xffffffffu, bi, off);
                if (ov > bv || (ov == bv && oi < bi)) { bv = ov; bi = oi; }
            }
            if (lid == r) myc = bi;
            if (bi == lid)      v0 = -1.f;
            if (bi == lid + 32) v1 = -1.f;
        }
        float ex = -INFINITY;
        if (lid < 12) {
            ex = 0.f;
            const float* xp = x + (size_t)(m0 + tl) * H;
            const float* wp = w + (size_t)myc * H;
            for (int k = 0; k < H; k += 8) {
                float4 xa = *(const float4*)(xp + k);
                float4 xb = *(const float4*)(xp + k + 4);
                float4 wa = *(const float4*)(wp + k);
                float4 wb = *(const float4*)(wp + k + 4);
                ex = fmaf(xa.x, wa.x, ex); ex = fmaf(xa.y, wa.y, ex);
                ex = fmaf(xa.z, wa.z, ex); ex = fmaf(xa.w, wa.w, ex);
                ex = fmaf(xb.x, wb.x, ex); ex = fmaf(xb.y, wb.y, ex);
                ex = fmaf(xb.z, wb.z, ex); ex = fmaf(xb.w, wb.w, ex);
            }
        }
        float exs[12]; int ids[12];
#pragma unroll
        for (int j = 0; j < 12; j++) {
            exs[j] = __shfl_sync(0xffffffffu, ex, j);
            ids[j] = __shfl_sync(0xffffffffu, myc, j);
        }
        if (lid == 0) {
            bool taken[12];
#pragma unroll
            for (int j = 0; j < 12; j++) taken[j] = false;
            float tsum = 0.f;
            float pw8[KTOP]; int pi8[KTOP];
            for (int k = 0; k < KTOP; k++) {
                int best = -1;
                for (int j = 0; j < 12; j++) {
                    if (taken[j]) continue;
                    if (best < 0 || exs[j] > exs[best] ||
                        (exs[j] == exs[best] && ids[j] < ids[best])) best = j;
                }
                taken[best] = true;
                pi8[k] = ids[best];
                pw8[k] = ls[tl][ids[best]];
                tsum += pw8[k];
            }
            const float invw = 1.f / (tsum + 1e-20f);
            const size_t t = (size_t)m0 + tl;
            for (int k = 0; k < KTOP; k++) {
                out[t * KTOP + k]                       = (float)pi8[k];
                out[(size_t)NTOK * KTOP + t * KTOP + k] = pw8[k] * invw;
                atomicAdd(&cnt[pi8[k]], 1);
            }
        }
    }
    __syncthreads();

    // ---------------- per-block partials ----------------
    if (tid < E) {
        float s = 0.f;
        for (int t = 0; t < MT; t++) s += ls[t][tid];
        g_ssum[blockIdx.x][tid] = s;
        g_cnt [blockIdx.x][tid] = (float)cnt[tid];
    }
    __threadfence();
    __syncthreads();
    if (tid == 0) islast = (atomicAdd(&g_done, 1) == NBLK - 1);
    __syncthreads();

    // ---------------- fused aux reduction (last block) ----------------
    if (islast) {
        __threadfence();
        const int b = tid >> 6;
        const int e = tid & 63;
        float ss = 0.f, cc = 0.f;
        const int base = b * (NBLK / BATCH);
#pragma unroll
        for (int blk = 0; blk < NBLK / BATCH; blk++) {
            ss += g_ssum[base + blk][e];
            cc += g_cnt [base + blk][e];
        }
        part[tid] = (cc * ((float)E / (float)(SEQ * KTOP))) * (ss * (1.f / (float)SEQ));
        __syncthreads();
#pragma unroll
        for (int stride = 128; stride > 0; stride >>= 1) {
            if (tid < stride) part[tid] += part[tid + stride];
            __syncthreads();
        }
        if (tid == 0) {
            out[2 * (size_t)NTOK * KTOP] = part[0] * (0.1f / (float)BATCH);
            g_done = 0;
        }
    }
}

extern "C" void kernel_launch(void* const* d_in, const int* in_sizes, int n_in,
                              void* d_out, int out_size)
{
    const float* x = (const float*)d_in[0];   // hidden_states [4,4096,2048]
    const float* w = (const float*)d_in[1];   // weight        [64,2048]
    float* out = (float*)d_out;

    wsplit_kernel<<<64, 256>>>(w);
    cudaFuncSetAttribute(gate_kernel, cudaFuncAttributeMaxDynamicSharedMemorySize, SMEM_BYTES);
    gate_kernel<<<NBLK, NTHR, SMEM_BYTES>>>(x, w, out);
}

// round 17
// speedup vs baseline: 3.0675x; 1.1642x over previous
#include <cuda_runtime.h>
#include <cuda_bf16.h>
#include <cstdint>
#include <math.h>

#define H      2048
#define E      64
#define KTOP   8
#define NTOK   16384
#define SEQ    4096
#define BATCH  4
#define MT     64
#define NBLK   (NTOK / MT)     // 256 CTAs
#define NTHR   256
#define NCH    32              // K chunks of 64
#define GAPTH  8e-6f
#define LSTR   66

// dynamic smem: two 16KB X buffers (Xhi 8K | Xlo 8K)
#define OFF_BUF  1024
#define XA1      0
#define XA2      8192
#define BUF_SZ   16384
#define SMEM_BYTES (OFF_BUF + 2 * BUF_SZ)   // 33792

typedef unsigned long long ull;

__device__ float    g_ssum[NBLK][E];
__device__ float    g_cnt [NBLK][E];
__device__ int      g_done;
// W in mma-B-fragment layout: [chunk][kquarter][ngroup][part][lane], part: 0-1 hi, 2-3 lo
__device__ __align__(16) uint4 g_wfrag[NCH][4][2][4][32];   // 512KB

// ---------------- helpers ----------------
__device__ __forceinline__ uint32_t smem_u32(const void* p) {
    uint32_t a;
    asm("{ .reg .u64 t; cvta.to.shared.u64 t, %1; cvt.u32.u64 %0, t; }" : "=r"(a) : "l"(p));
    return a;
}
__device__ __forceinline__ uint32_t swz(uint32_t b) { return b ^ ((b >> 3) & 0x70); }

__device__ __forceinline__ void split2(float f0, float f1, uint32_t& hi, uint32_t& lo) {
    uint32_t h;
    asm("cvt.rn.bf16x2.f32 %0, %1, %2;" : "=r"(h) : "f"(f1), "f"(f0));
    float g0 = __uint_as_float(h << 16);
    float g1 = __uint_as_float(h & 0xFFFF0000u);
    asm("cvt.rn.bf16x2.f32 %0, %1, %2;" : "=r"(lo) : "f"(f1 - g1), "f"(f0 - g0));
    hi = h;
}
__device__ __forceinline__ void ldsm4(uint32_t* r, uint32_t addr) {
    asm volatile("ldmatrix.sync.aligned.m8n8.x4.shared.b16 {%0,%1,%2,%3}, [%4];"
        : "=r"(r[0]), "=r"(r[1]), "=r"(r[2]), "=r"(r[3]) : "r"(addr));
}
__device__ __forceinline__ void mma16816(float* d, const uint32_t* a, const uint32_t* b) {
    asm("mma.sync.aligned.m16n8k16.row.col.f32.bf16.bf16.f32 "
        "{%0,%1,%2,%3}, {%4,%5,%6,%7}, {%8,%9}, {%0,%1,%2,%3};"
        : "+f"(d[0]), "+f"(d[1]), "+f"(d[2]), "+f"(d[3])
        : "r"(a[0]), "r"(a[1]), "r"(a[2]), "r"(a[3]), "r"(b[0]), "r"(b[1]));
}
__device__ __forceinline__ void conv4(const float4 v, uint32_t* h, uint32_t* l) {
    split2(v.x, v.y, h[0], l[0]);
    split2(v.z, v.w, h[1], l[1]);
}
// ------------------------------------------

// Pre-split W into per-lane mma B-fragments (hi/lo).
__global__ __launch_bounds__(256, 1)
void wfrag_kernel(const float* __restrict__ w)
{
    const int idx  = blockIdx.x * 256 + threadIdx.x;   // 0..8191
    const int lane = idx & 31;
    const int g    = (idx >> 5) & 1;
    const int q    = (idx >> 6) & 3;
    const int c    = idx >> 8;

    uint32_t hi[8], lo[8];
#pragma unroll
    for (int t = 0; t < 4; t++) {
        const int n  = g * 32 + t * 8 + (lane >> 2);
        const int kb = c * 64 + q * 16 + (lane & 3) * 2;
        const float* wp = w + (size_t)n * H + kb;
        split2(wp[0], wp[1], hi[t * 2],     lo[t * 2]);
        split2(wp[8], wp[9], hi[t * 2 + 1], lo[t * 2 + 1]);
    }
    g_wfrag[c][q][g][0][lane] = make_uint4(hi[0], hi[1], hi[2], hi[3]);
    g_wfrag[c][q][g][1][lane] = make_uint4(hi[4], hi[5], hi[6], hi[7]);
    g_wfrag[c][q][g][2][lane] = make_uint4(lo[0], lo[1], lo[2], lo[3]);
    g_wfrag[c][q][g][3][lane] = make_uint4(lo[4], lo[5], lo[6], lo[7]);
}

__global__ __launch_bounds__(NTHR, 2)
void gate_kernel(const float* __restrict__ x,
                 const float* __restrict__ w,
                 float* __restrict__ out)
{
    extern __shared__ __align__(1024) char smem[];
    __shared__ __align__(16) float part[NTHR];
    __shared__ int cnt[E];
    __shared__ int nflag, flist[MT], islast;

    const uint32_t sb = smem_u32(smem);
    const int tid = threadIdx.x;
    const int wid = tid >> 5;
    const int lid = tid & 31;
    const int m0  = blockIdx.x * MT;

    if (tid == 0) nflag = 0;
    if (tid < E) cnt[tid] = 0;

    // ---------------- producer mapping (X tile 64x64 fp32) ----------------
    const int pr = tid >> 2;            // token row 0..63
    const int pq = tid & 3;             // 16-col quarter
    const float* xrow = x + (size_t)(m0 + pr) * H + pq * 16;
    const uint32_t sto0 = swz((uint32_t)(pr * 128 + pq * 32));
    const uint32_t sto1 = swz((uint32_t)(pr * 128 + pq * 32 + 16));

    // ------------- consumer mapping: warp = (kquarter, ngroup), m64 --------
    const int q = wid & 3;              // k-quarter 0..3
    const int g = wid >> 2;             // n-group 0..1
    const int arow = lid & 15;
    const int akh  = lid >> 4;
    uint32_t relA[4];
#pragma unroll
    for (int mi = 0; mi < 4; mi++)
        relA[mi] = swz((uint32_t)((mi * 16 + arow) * 128 + akh * 16));
    const uint32_t kx = (uint32_t)(q << 5);

    float acc[4][4][4];                 // [m16 tile][n8 tile][4]
#pragma unroll
    for (int mi = 0; mi < 4; mi++)
#pragma unroll
        for (int t = 0; t < 4; t++)
#pragma unroll
            for (int r = 0; r < 4; r++) acc[mi][t][r] = 0.f;

    float4 xv[4];
#pragma unroll
    for (int i = 0; i < 4; i++) xv[i] = *(const float4*)(xrow + i * 4);

    // ---------------- mainloop ----------------
    for (int c = 0; c < NCH; c++) {
        char* buf = smem + OFF_BUF + (c & 1) * BUF_SZ;
        {
            uint32_t h[4], l[4];
            conv4(xv[0], h, l); conv4(xv[1], h + 2, l + 2);
            *(uint4*)(buf + XA1 + sto0) = make_uint4(h[0], h[1], h[2], h[3]);
            *(uint4*)(buf + XA2 + sto0) = make_uint4(l[0], l[1], l[2], l[3]);
            conv4(xv[2], h, l); conv4(xv[3], h + 2, l + 2);
            *(uint4*)(buf + XA1 + sto1) = make_uint4(h[0], h[1], h[2], h[3]);
            *(uint4*)(buf + XA2 + sto1) = make_uint4(l[0], l[1], l[2], l[3]);
        }
        if (c + 1 < NCH) {
            const float* xp = xrow + (c + 1) * 64;
#pragma unroll
            for (int i = 0; i < 4; i++) xv[i] = *(const float4*)(xp + i * 4);
        }

        // B fragments direct from global (coalesced LDG.128 x4 per warp)
        const uint4* wfp = &g_wfrag[c][q][g][0][lid];
        uint4 bh0 = wfp[0];
        uint4 bh1 = wfp[32];
        uint4 bl0 = wfp[64];
        uint4 bl1 = wfp[96];
        uint32_t bhi[8] = {bh0.x, bh0.y, bh0.z, bh0.w, bh1.x, bh1.y, bh1.z, bh1.w};
        uint32_t blo[8] = {bl0.x, bl0.y, bl0.z, bl0.w, bl1.x, bl1.y, bl1.z, bl1.w};

        __syncthreads();

        const uint32_t bufb = sb + OFF_BUF + (uint32_t)(c & 1) * BUF_SZ;
#pragma unroll
        for (int mi = 0; mi < 4; mi++) {
            uint32_t a1[4], a2[4];
            ldsm4(a1, bufb + XA1 + (relA[mi] ^ kx));
            ldsm4(a2, bufb + XA2 + (relA[mi] ^ kx));
#pragma unroll
            for (int t = 0; t < 4; t++) {
                mma16816(acc[mi][t], a1, &bhi[t * 2]);
                mma16816(acc[mi][t], a2, &bhi[t * 2]);
                mma16816(acc[mi][t], a1, &blo[t * 2]);
            }
        }
    }

    // ---------------- logits regs -> smem (4-phase k-quarter merge) --------
    float (*ls)[LSTR] = reinterpret_cast<float(*)[LSTR]>(smem + OFF_BUF);
    const int r0 = lid >> 2, c0 = 2 * (lid & 3);
    __syncthreads();
#pragma unroll
    for (int qq = 0; qq < 4; qq++) {
        if (q == qq) {
#pragma unroll
            for (int mi = 0; mi < 4; mi++)
#pragma unroll
                for (int t = 0; t < 4; t++) {
                    const int mr = mi * 16 + r0;
                    const int nc = g * 32 + t * 8 + c0;
                    if (qq == 0) {
                        *(float2*)&ls[mr][nc]     = make_float2(acc[mi][t][0], acc[mi][t][1]);
                        *(float2*)&ls[mr + 8][nc] = make_float2(acc[mi][t][2], acc[mi][t][3]);
                    } else {
                        float2 p0 = *(const float2*)&ls[mr][nc];
                        float2 p1 = *(const float2*)&ls[mr + 8][nc];
                        *(float2*)&ls[mr][nc]     = make_float2(p0.x + acc[mi][t][0], p0.y + acc[mi][t][1]);
                        *(float2*)&ls[mr + 8][nc] = make_float2(p1.x + acc[mi][t][2], p1.y + acc[mi][t][3]);
                    }
                }
        }
        __syncthreads();
    }

    // ---------------- per-token epilogue (single-pass top-9) + flagging ----
    if (tid < MT) {
        float mx = -INFINITY;
#pragma unroll 8
        for (int e = 0; e < E; e++) mx = fmaxf(mx, ls[tid][e]);
        float s = 0.f;
#pragma unroll 8
        for (int e = 0; e < E; e++) {
            float v = expf(ls[tid][e] - mx);
            s += v;
            ls[tid][e] = v;
        }
        const float inv = 1.f / s;

        float pw[9]; int pi[9];
#pragma unroll
        for (int k = 0; k < 9; k++) { pw[k] = -1.f; pi[k] = 0; }
        for (int e = 0; e < E; e++) {
            float v = ls[tid][e] * inv;
            ls[tid][e] = v;
            if (v > pw[8]) {
                int j = 8;
#pragma unroll 8
                while (j > 0 && v > pw[j - 1]) {
                    pw[j] = pw[j - 1]; pi[j] = pi[j - 1]; j--;
                }
                pw[j] = v; pi[j] = e;
            }
        }
        float ming = 1e30f;
#pragma unroll
        for (int k = 0; k < 8; k++) ming = fminf(ming, pw[k] - pw[k + 1]);

        if (ming < GAPTH) {
            int p = atomicAdd(&nflag, 1);
            flist[p] = tid;
        } else {
            float tsum = 0.f;
#pragma unroll
            for (int k = 0; k < KTOP; k++) tsum += pw[k];
            const float invw = 1.f / (tsum + 1e-20f);
            const size_t t = (size_t)m0 + tid;
#pragma unroll
            for (int k = 0; k < KTOP; k++) {
                out[t * KTOP + k]                       = (float)pi[k];
                out[(size_t)NTOK * KTOP + t * KTOP + k] = pw[k] * invw;
                atomicAdd(&cnt[pi[k]], 1);
            }
        }
    }
    __syncthreads();

    // ---------------- warp-parallel exact fixup (top-12 candidates) --------
    for (int i = wid; i < nflag; i += 8) {
        const int tl = flist[i];
        float v0 = ls[tl][lid];
        float v1 = ls[tl][lid + 32];
        int myc = 0;
#pragma unroll
        for (int r = 0; r < 12; r++) {
            float bv; int bi;
            if (v0 >= v1) { bv = v0; bi = lid; } else { bv = v1; bi = lid + 32; }
#pragma unroll
            for (int off = 16; off; off >>= 1) {
                float ov = __shfl_xor_sync(0xffffffffu, bv, off);
                int   oi = __shfl_xor_sync(0xffffffffu, bi, off);
                if (ov > bv || (ov == bv && oi < bi)) { bv = ov; bi = oi; }
            }
            if (lid == r) myc = bi;
            if (bi == lid)      v0 = -1.f;
            if (bi == lid + 32) v1 = -1.f;
        }
        float ex = -INFINITY;
        if (lid < 12) {
            ex = 0.f;
            const float* xp = x + (size_t)(m0 + tl) * H;
            const float* wp = w + (size_t)myc * H;
            for (int k = 0; k < H; k += 8) {
                float4 xa = *(const float4*)(xp + k);
                float4 xb = *(const float4*)(xp + k + 4);
                float4 wa = *(const float4*)(wp + k);
                float4 wb = *(const float4*)(wp + k + 4);
                ex = fmaf(xa.x, wa.x, ex); ex = fmaf(xa.y, wa.y, ex);
                ex = fmaf(xa.z, wa.z, ex); ex = fmaf(xa.w, wa.w, ex);
                ex = fmaf(xb.x, wb.x, ex); ex = fmaf(xb.y, wb.y, ex);
                ex = fmaf(xb.z, wb.z, ex); ex = fmaf(xb.w, wb.w, ex);
            }
        }
        float exs[12]; int ids[12];
#pragma unroll
        for (int j = 0; j < 12; j++) {
            exs[j] = __shfl_sync(0xffffffffu, ex, j);
            ids[j] = __shfl_sync(0xffffffffu, myc, j);
        }
        if (lid == 0) {
            bool taken[12];
#pragma unroll
            for (int j = 0; j < 12; j++) taken[j] = false;
            float tsum = 0.f;
            float pw8[KTOP]; int pi8[KTOP];
            for (int k = 0; k < KTOP; k++) {
                int best = -1;
                for (int j = 0; j < 12; j++) {
                    if (taken[j]) continue;
                    if (best < 0 || exs[j] > exs[best] ||
                        (exs[j] == exs[best] && ids[j] < ids[best])) best = j;
                }
                taken[best] = true;
                pi8[k] = ids[best];
                pw8[k] = ls[tl][ids[best]];
                tsum += pw8[k];
            }
            const float invw = 1.f / (tsum + 1e-20f);
            const size_t t = (size_t)m0 + tl;
            for (int k = 0; k < KTOP; k++) {
                out[t * KTOP + k]                       = (float)pi8[k];
                out[(size_t)NTOK * KTOP + t * KTOP + k] = pw8[k] * invw;
                atomicAdd(&cnt[pi8[k]], 1);
            }
        }
    }
    __syncthreads();

    // ---------------- per-block partials ----------------
    if (tid < E) {
        float s = 0.f;
        for (int t = 0; t < MT; t++) s += ls[t][tid];
        g_ssum[blockIdx.x][tid] = s;
        g_cnt [blockIdx.x][tid] = (float)cnt[tid];
    }
    __threadfence();
    __syncthreads();
    if (tid == 0) islast = (atomicAdd(&g_done, 1) == NBLK - 1);
    __syncthreads();

    // ---------------- fused aux reduction (last block) ----------------
    if (islast) {
        __threadfence();
        const int b = tid >> 6;
        const int e = tid & 63;
        float ss = 0.f, cc = 0.f;
        const int base = b * (NBLK / BATCH);
#pragma unroll
        for (int blk = 0; blk < NBLK / BATCH; blk++) {
            ss += g_ssum[base + blk][e];
            cc += g_cnt [base + blk][e];
        }
        part[tid] = (cc * ((float)E / (float)(SEQ * KTOP))) * (ss * (1.f / (float)SEQ));
        __syncthreads();
#pragma unroll
        for (int stride = 128; stride > 0; stride >>= 1) {
            if (tid < stride) part[tid] += part[tid + stride];
            __syncthreads();
        }
        if (tid == 0) {
            out[2 * (size_t)NTOK * KTOP] = part[0] * (0.1f / (float)BATCH);
            g_done = 0;
        }
    }
}

extern "C" void kernel_launch(void* const* d_in, const int* in_sizes, int n_in,
                              void* d_out, int out_size)
{
    const float* x = (const float*)d_in[0];   // hidden_states [4,4096,2048]
    const float* w = (const float*)d_in[1];   // weight        [64,2048]
    float* out = (float*)d_out;

    wfrag_kernel<<<32, 256>>>(w);
    cudaFuncSetAttribute(gate_kernel, cudaFuncAttributeMaxDynamicSharedMemorySize, SMEM_BYTES);
    gate_kernel<<<NBLK, NTHR, SMEM_BYTES>>>(x, w, out);
}